// round 10
// baseline (speedup 1.0000x reference)
#include <cuda_runtime.h>
#include <cuda_fp16.h>
#include <math.h>
#include <stdint.h>

// Problem constants
#define B_  4
#define S_  1024
#define D_  1024
#define H_  16
#define DKH_ 32
#define DV_  64

// ---------------------------------------------------------------------------
// Scratch (device globals; no allocations allowed)
// ---------------------------------------------------------------------------
__device__ __half pQh[4096*512],  pQl[4096*512];
__device__ __half pKh[4096*512],  pKl[4096*512];
__device__ __half pVh_[4096*1024];
__device__ __half pWh[6*512*512];
__device__ __half g_Q1h[64*1024*32], g_Q1l[64*1024*32];  // pre-scaled
__device__ __half g_K1h[64*1024*32], g_K1l[64*1024*32];
__device__ __half g_Vh [64*1024*64];
__device__ __half qkvh[4096*1024];
__device__ float g_tmp[B_*S_*D_];

// ===========================================================================
// helpers
// ===========================================================================
__device__ __forceinline__ uint32_t smem_u32(const void* p) {
    uint32_t a;
    asm("{ .reg .u64 t; cvta.to.shared.u64 t, %1; cvt.u32.u64 %0, t; }"
        : "=r"(a) : "l"(p));
    return a;
}
__device__ __forceinline__ void ldsm_x4(uint32_t& r0, uint32_t& r1,
                                        uint32_t& r2, uint32_t& r3, uint32_t addr) {
    asm volatile("ldmatrix.sync.aligned.m8n8.x4.shared.b16 {%0,%1,%2,%3}, [%4];"
                 : "=r"(r0), "=r"(r1), "=r"(r2), "=r"(r3) : "r"(addr));
}
__device__ __forceinline__ void ldsm_x2(uint32_t& r0, uint32_t& r1, uint32_t addr) {
    asm volatile("ldmatrix.sync.aligned.m8n8.x2.shared.b16 {%0,%1}, [%2];"
                 : "=r"(r0), "=r"(r1) : "r"(addr));
}
__device__ __forceinline__ void ldsm_x2t(uint32_t& r0, uint32_t& r1, uint32_t addr) {
    asm volatile("ldmatrix.sync.aligned.m8n8.x2.trans.shared.b16 {%0,%1}, [%2];"
                 : "=r"(r0), "=r"(r1) : "r"(addr));
}
__device__ __forceinline__ void mma_f16(float* c, uint32_t a0, uint32_t a1,
                                        uint32_t a2, uint32_t a3,
                                        uint32_t b0, uint32_t b1) {
    asm volatile("mma.sync.aligned.m16n8k16.row.col.f32.f16.f16.f32 "
                 "{%0,%1,%2,%3}, {%4,%5,%6,%7}, {%8,%9}, {%0,%1,%2,%3};"
                 : "+f"(c[0]), "+f"(c[1]), "+f"(c[2]), "+f"(c[3])
                 : "r"(a0), "r"(a1), "r"(a2), "r"(a3), "r"(b0), "r"(b1));
}
__device__ __forceinline__ uint32_t pack_h2(float x, float y) {
    __half2 t = __floats2half2_rn(x, y);
    return *reinterpret_cast<uint32_t*>(&t);
}
__device__ __forceinline__ void split2h(float x, float y, uint32_t& hi, uint32_t& lo) {
    __half hx = __float2half_rn(x);
    __half hy = __float2half_rn(y);
    __half2 h; h.x = hx; h.y = hy;
    hi = *reinterpret_cast<uint32_t*>(&h);
    lo = pack_h2(x - __half2float(hx), y - __half2float(hy));
}
__device__ __forceinline__ void cp16(uint32_t dst, const void* src) {
    asm volatile("cp.async.cg.shared.global [%0], [%1], 16;"
                 :: "r"(dst), "l"(src));
}
#define CP_COMMIT()  asm volatile("cp.async.commit_group;" ::: "memory")
#define CP_WAIT(N)   asm volatile("cp.async.wait_group %0;" :: "n"(N) : "memory")

// ===========================================================================
// presplit: fp32 -> fp16 for all GEMM operands.
// ===========================================================================
__global__ void __launch_bounds__(256)
presplit(const float* __restrict__ inQ, const float* __restrict__ inK,
         const float* __restrict__ inV,
         const float* __restrict__ W0, const float* __restrict__ W1,
         const float* __restrict__ W2, const float* __restrict__ W3,
         const float* __restrict__ W4, const float* __restrict__ W5)
{
    const int seg = blockIdx.y;
    const int gid = blockIdx.x * 256 + threadIdx.x;
    const int stride4 = gridDim.x * 256 * 4;

    if (seg < 2) {
        const float* s = seg ? inK : inQ;
        __half* dh = seg ? pKh : pQh;
        __half* dl = seg ? pKl : pQl;
        for (int i = gid * 4; i < 4096 * 512; i += stride4) {
            int row = i >> 9, col = i & 511;
            float4 v = *(const float4*)&s[(size_t)row * 1024 + col];
            uint32_t h0, l0, h1, l1;
            split2h(v.x, v.y, h0, l0); split2h(v.z, v.w, h1, l1);
            *(uint2*)&dh[i] = make_uint2(h0, h1);
            *(uint2*)&dl[i] = make_uint2(l0, l1);
        }
    } else if (seg == 2) {
        for (int i = gid * 4; i < 4096 * 1024; i += stride4) {
            float4 v = *(const float4*)&inV[i];
            *(uint2*)&pVh_[i] = make_uint2(pack_h2(v.x, v.y), pack_h2(v.z, v.w));
        }
    } else {
        const int w = seg - 3;
        const float* s = (w == 0) ? W0 : (w == 1) ? W1 : (w == 2) ? W2
                       : (w == 3) ? W3 : (w == 4) ? W4 : W5;
        __half* dh = pWh + (size_t)w * 262144;
        for (int i = gid * 4; i < 262144; i += stride4) {
            float4 v = *(const float4*)&s[i];
            *(uint2*)&dh[i] = make_uint2(pack_h2(v.x, v.y), pack_h2(v.z, v.w));
        }
    }
}

// ===========================================================================
// HMMA GEMM (unchanged from R9): 512 threads, 128x128 tile, 3-stage pipeline.
//   NT=2: (Ah + Al) x Wh   (modes 0,1: Q1,K1 proj)
//   NT=1:  Ah x Wh         (modes 2,3: V proj; 4,5: FC + residual)
// ===========================================================================
#define APITCH 80
#define BPITCH 272
#define ST_SZ  29184u
#define ST_AH(s) ((s) * ST_SZ)
#define ST_AL(s) ((s) * ST_SZ + 10240u)
#define ST_BH(s) ((s) * ST_SZ + 20480u)
#define GEMM_SMEM (3 * 29184)

template<int NT>
__global__ void __launch_bounds__(512, 1)
mma_gemm(const float* __restrict__ inQ, int mode_base)
{
    extern __shared__ unsigned char sm[];
    const uint32_t smb = smem_u32(sm);

    const int mode = mode_base + blockIdx.z;
    const __half *pAh, *pAl;
    int apitch, aoff;
    switch (mode) {
        case 0: pAh = pQh;  pAl = pQl;  apitch = 512;  aoff = 0;   break;
        case 1: pAh = pKh;  pAl = pKl;  apitch = 512;  aoff = 0;   break;
        case 2: pAh = pVh_; pAl = pVh_; apitch = 1024; aoff = 0;   break;
        case 3: pAh = pVh_; pAl = pVh_; apitch = 1024; aoff = 512; break;
        case 4: pAh = qkvh; pAl = qkvh; apitch = 1024; aoff = 0;   break;
        default:pAh = qkvh; pAl = qkvh; apitch = 1024; aoff = 512; break;
    }
    const __half* wh = pWh + (size_t)mode * 262144;

    const int m0 = blockIdx.x * 128;
    const int n0 = blockIdx.y * 128;
    const int tid  = threadIdx.x;
    const int wid  = tid >> 5;
    const int lane = tid & 31;
    const int wy = wid >> 2;
    const int wx = wid & 3;

    const int ar = tid >> 2, aseg = tid & 3;
    const int br = tid >> 4, bseg = tid & 15;

    #define GFILL(st, k0)                                                         \
    {                                                                             \
        const __half* sha = pAh + (size_t)(m0 + ar) * apitch + aoff + (k0) + aseg * 8; \
        uint32_t da = (uint32_t)(ar * APITCH + aseg * 16);                        \
        cp16(smb + ST_AH(st) + da, sha);                                          \
        if (NT == 2) {                                                            \
            const __half* sla = pAl + (size_t)(m0 + ar) * apitch + aoff + (k0) + aseg * 8; \
            cp16(smb + ST_AL(st) + da, sla);                                      \
        }                                                                         \
        const __half* shb = wh + (size_t)((k0) + br) * 512 + n0 + bseg * 8;       \
        uint32_t db = (uint32_t)(br * BPITCH + bseg * 16);                        \
        cp16(smb + ST_BH(st) + db, shb);                                          \
        CP_COMMIT();                                                              \
    }

    float c[2][4][4] = {};

    const int a_row_in_tile = lane & 15;
    const int a_kseg        = (lane >> 4) & 1;
    const int b_krow        = (lane & 7) + ((lane >> 3) & 1) * 8;

    GFILL(0, 0);
    GFILL(1, 32);

    for (int chunk = 0; chunk < 16; ++chunk) {
        if (chunk + 1 < 16) { CP_WAIT(1); } else { CP_WAIT(0); }
        __syncthreads();
        if (chunk + 2 < 16) {
            int st = (chunk + 2) % 3;
            GFILL(st, (chunk + 2) * 32);
        }
        const int cs = chunk % 3;
        const uint32_t ahb = smb + ST_AH(cs);
        const uint32_t alb = smb + ST_AL(cs);
        const uint32_t bhb = smb + ST_BH(cs);

        #pragma unroll
        for (int ks = 0; ks < 2; ++ks) {
            uint32_t ahf[2][4], alf[2][4];
            #pragma unroll
            for (int mt = 0; mt < 2; ++mt) {
                int row = wy * 32 + mt * 16 + a_row_in_tile;
                uint32_t aoffb = (uint32_t)(row * APITCH + ks * 32 + a_kseg * 16);
                ldsm_x4(ahf[mt][0], ahf[mt][1], ahf[mt][2], ahf[mt][3], ahb + aoffb);
                if (NT == 2)
                    ldsm_x4(alf[mt][0], alf[mt][1], alf[mt][2], alf[mt][3], alb + aoffb);
            }
            uint32_t bhf[4][2];
            #pragma unroll
            for (int nt = 0; nt < 4; ++nt) {
                uint32_t boffb = (uint32_t)((ks * 16 + b_krow) * BPITCH
                                            + (wx * 32 + nt * 8) * 2);
                ldsm_x2t(bhf[nt][0], bhf[nt][1], bhb + boffb);
            }
            #pragma unroll
            for (int mt = 0; mt < 2; ++mt) {
                #pragma unroll
                for (int nt = 0; nt < 4; ++nt) {
                    mma_f16(c[mt][nt], ahf[mt][0], ahf[mt][1], ahf[mt][2], ahf[mt][3],
                            bhf[nt][0], bhf[nt][1]);
                    if (NT == 2)
                        mma_f16(c[mt][nt], alf[mt][0], alf[mt][1], alf[mt][2], alf[mt][3],
                                bhf[nt][0], bhf[nt][1]);
                }
            }
        }
    }

    // ---- epilogue ----
    const int gid = lane >> 2;
    const int tig = lane & 3;

    #pragma unroll
    for (int mt = 0; mt < 2; ++mt) {
        int row = m0 + wy * 32 + mt * 16 + gid;
        int b = row >> 10, s = row & 1023;
        #pragma unroll
        for (int nt = 0; nt < 4; ++nt) {
            int col = n0 + wx * 32 + nt * 8 + tig * 2;
            float2 v01 = make_float2(c[mt][nt][0], c[mt][nt][1]);
            float2 v23 = make_float2(c[mt][nt][2], c[mt][nt][3]);
            if (mode <= 1) {
                int h = col >> 5, d = col & 31;
                __half* dh = (mode == 0) ? g_Q1h : g_K1h;
                __half* dl = (mode == 0) ? g_Q1l : g_K1l;
                float sc = (mode == 0) ? 0.17677669529663688f : 1.0f;
                size_t base = ((size_t)(b * 16 + h) * 1024) * 32 + d;
                uint32_t hi, lo;
                split2h(v01.x * sc, v01.y * sc, hi, lo);
                *(uint32_t*)&dh[base + (size_t)s * 32] = hi;
                *(uint32_t*)&dl[base + (size_t)s * 32] = lo;
                split2h(v23.x * sc, v23.y * sc, hi, lo);
                *(uint32_t*)&dh[base + (size_t)(s + 8) * 32] = hi;
                *(uint32_t*)&dl[base + (size_t)(s + 8) * 32] = lo;
            } else if (mode <= 3) {
                int h = col >> 5, d = (col & 31) + (mode == 3 ? 32 : 0);
                size_t base = ((size_t)(b * 16 + h) * 1024) * 64 + d;
                *(uint32_t*)&g_Vh[base + (size_t)s * 64]       = pack_h2(v01.x, v01.y);
                *(uint32_t*)&g_Vh[base + (size_t)(s + 8) * 64] = pack_h2(v23.x, v23.y);
            } else {
                int half = mode - 4;
                size_t idx0 = (size_t)row * 1024 + half * 512 + col;
                size_t idx1 = idx0 + 8 * 1024;
                float2 r0 = *(const float2*)&inQ[idx0];
                float2 r1 = *(const float2*)&inQ[idx1];
                *(float2*)&g_tmp[idx0] = make_float2(v01.x + r0.x, v01.y + r0.y);
                *(float2*)&g_tmp[idx1] = make_float2(v23.x + r1.x, v23.y + r1.y);
            }
        }
    }
    #undef GFILL
}

// ===========================================================================
// Flash attention, paired causal slabs: CTA = (bh, qy) handles slab qy AND
// slab 15-qy -> constant 17 tiles/CTA, 512 CTAs, single balanced wave.
// Pass1: QK 1-term -> l. Pass2: QK 3-term -> P write + PV 1-term.
// ===========================================================================
#define AT_K_H(buf) ((buf) * 5120u)
#define AT_K_L(buf) (10240u + (buf) * 5120u)
#define AT_V_H(buf) (20480u + (buf) * 9216u)
#define AT_Q_H 20480u
#define AT_Q_L 25600u
#define ATTN_SMEM 38912

__global__ void __launch_bounds__(128, 4)
attn_flash(float* __restrict__ Pout)
{
    extern __shared__ unsigned char sm[];
    const uint32_t smb = smem_u32(sm);

    const int bh = blockIdx.x;
    const int qy = blockIdx.y;             // 0..7
    const int tid = threadIdx.x, wid = tid >> 5, lane = tid & 31;

    const int frow = tid >> 1;
    const int fs2  = (tid & 1) * 2;
    const int fs4  = (tid & 1) * 4;

#define KFILL(buf, kt, withlo)                                                    \
    {                                                                             \
        const __half* sh_ = g_K1h + ((size_t)bh*1024 + (size_t)(kt)*64 + frow)*32 + fs2*8; \
        uint32_t d_ = (uint32_t)(frow * 80 + fs2 * 16);                           \
        cp16(smb + AT_K_H(buf) + d_,      sh_);                                   \
        cp16(smb + AT_K_H(buf) + d_ + 16, sh_ + 8);                               \
        if (withlo) {                                                             \
            const __half* sl_ = g_K1l + ((size_t)bh*1024 + (size_t)(kt)*64 + frow)*32 + fs2*8; \
            cp16(smb + AT_K_L(buf) + d_,      sl_);                               \
            cp16(smb + AT_K_L(buf) + d_ + 16, sl_ + 8);                           \
        }                                                                         \
    }
#define VFILL(buf, kt)                                                            \
    {                                                                             \
        const __half* sh_ = g_Vh + ((size_t)bh*1024 + (size_t)(kt)*64 + frow)*64 + fs4*8; \
        uint32_t d_ = (uint32_t)(frow * 144 + fs4 * 16);                          \
        _Pragma("unroll")                                                         \
        for (int u_ = 0; u_ < 4; ++u_)                                            \
            cp16(smb + AT_V_H(buf) + d_ + u_*16, sh_ + u_*8);                     \
    }

    #define SCOMP1(buf)                                                           \
    {                                                                             \
        const uint32_t khb = smb + AT_K_H(buf);                                   \
        _Pragma("unroll")                                                         \
        for (int ks = 0; ks < 2; ++ks) {                                          \
            _Pragma("unroll")                                                     \
            for (int nt = 0; nt < 8; ++nt) {                                      \
                uint32_t boff = (uint32_t)((nt * 8 + (lane & 7)) * 80             \
                                           + ks * 32 + ((lane >> 3) & 1) * 16);   \
                uint32_t b0, b1;                                                  \
                ldsm_x2(b0, b1, khb + boff);                                      \
                mma_f16(s[nt], qfh[ks][0], qfh[ks][1], qfh[ks][2], qfh[ks][3], b0, b1); \
            }                                                                     \
        }                                                                         \
    }
    #define SCOMP3(buf)                                                           \
    {                                                                             \
        const uint32_t khb = smb + AT_K_H(buf);                                   \
        const uint32_t klb = smb + AT_K_L(buf);                                   \
        _Pragma("unroll")                                                         \
        for (int ks = 0; ks < 2; ++ks) {                                          \
            _Pragma("unroll")                                                     \
            for (int nt = 0; nt < 8; ++nt) {                                      \
                uint32_t boff = (uint32_t)((nt * 8 + (lane & 7)) * 80             \
                                           + ks * 32 + ((lane >> 3) & 1) * 16);   \
                uint32_t b0, b1, d0, d1;                                          \
                ldsm_x2(b0, b1, khb + boff);                                      \
                ldsm_x2(d0, d1, klb + boff);                                      \
                mma_f16(s[nt], qfh[ks][0], qfh[ks][1], qfh[ks][2], qfh[ks][3], b0, b1); \
                mma_f16(s[nt], qfh[ks][0], qfh[ks][1], qfh[ks][2], qfh[ks][3], d0, d1); \
                mma_f16(s[nt], qfl[ks][0], qfl[ks][1], qfl[ks][2], qfl[ks][3], b0, b1); \
            }                                                                     \
        }                                                                         \
    }
    #define SMASK(kt)                                                             \
    if ((kt) == nkt - 1) {                                                        \
        int cb = (kt) * 64 + (lane & 3) * 2;                                      \
        _Pragma("unroll")                                                         \
        for (int nt = 0; nt < 8; ++nt) {                                          \
            int c0 = cb + nt * 8;                                                 \
            if (c0     > gr0)     s[nt][0] = -1e30f;                              \
            if (c0 + 1 > gr0)     s[nt][1] = -1e30f;                              \
            if (c0     > gr0 + 8) s[nt][2] = -1e30f;                              \
            if (c0 + 1 > gr0 + 8) s[nt][3] = -1e30f;                              \
        }                                                                         \
    }

    for (int hp = 0; hp < 2; ++hp) {
        const int qs = hp ? (15 - qy) : qy;
        const int q0 = qs * 64;
        const int nkt = qs + 1;
        const int ncol = nkt * 64;

        // smem reused across slabs / passes: prior reads done before refill
        __syncthreads();
        KFILL(0, 0, false); CP_COMMIT();

        // stage Q slab (64 x 32 fp16 hi/lo)
        {
            const __half* qh = g_Q1h + ((size_t)bh*1024 + q0 + frow)*32 + fs2*8;
            const __half* ql = g_Q1l + ((size_t)bh*1024 + q0 + frow)*32 + fs2*8;
            uint32_t d = (uint32_t)(frow * 80 + fs2 * 16);
            *(uint4*)(sm + AT_Q_H + d)      = *(const uint4*)qh;
            *(uint4*)(sm + AT_Q_H + d + 16) = *(const uint4*)(qh + 8);
            *(uint4*)(sm + AT_Q_L + d)      = *(const uint4*)ql;
            *(uint4*)(sm + AT_Q_L + d + 16) = *(const uint4*)(ql + 8);
        }
        __syncthreads();

        uint32_t qfh[2][4], qfl[2][4];
        #pragma unroll
        for (int ks = 0; ks < 2; ++ks) {
            uint32_t off = (uint32_t)((wid * 16 + (lane & 15)) * 80
                                      + ks * 32 + ((lane >> 4) & 1) * 16);
            ldsm_x4(qfh[ks][0], qfh[ks][1], qfh[ks][2], qfh[ks][3], smb + AT_Q_H + off);
            ldsm_x4(qfl[ks][0], qfl[ks][1], qfl[ks][2], qfl[ks][3], smb + AT_Q_L + off);
        }

        const int gr0 = q0 + wid * 16 + (lane >> 2);

        // ================= Pass 1: l = sum exp(s), 1-term QK =================
        float l0 = 0.f, l1 = 0.f;

        for (int kt = 0; kt < nkt; ++kt) {
            CP_WAIT(0);
            __syncthreads();
            if (kt + 1 < nkt) { KFILL((kt + 1) & 1, kt + 1, false); CP_COMMIT(); }

            float s[8][4] = {};
            SCOMP1(kt & 1);
            SMASK(kt);

            float a0 = 0.f, a1 = 0.f;
            #pragma unroll
            for (int nt = 0; nt < 8; ++nt) {
                a0 += __expf(s[nt][0]) + __expf(s[nt][1]);
                a1 += __expf(s[nt][2]) + __expf(s[nt][3]);
            }
            a0 += __shfl_xor_sync(0xffffffffu, a0, 1);
            a0 += __shfl_xor_sync(0xffffffffu, a0, 2);
            a1 += __shfl_xor_sync(0xffffffffu, a1, 1);
            a1 += __shfl_xor_sync(0xffffffffu, a1, 2);
            l0 += a0;
            l1 += a1;
        }
        const float li0 = 1.0f / l0, li1 = 1.0f / l1;

        // ================= Pass 2: P write + O = P @ V =================
        __syncthreads();
        KFILL(0, 0, true); VFILL(0, 0); CP_COMMIT();

        float o[8][4] = {};

        for (int kt = 0; kt < nkt; ++kt) {
            CP_WAIT(0);
            __syncthreads();
            if (kt + 1 < nkt) {
                KFILL((kt + 1) & 1, kt + 1, true);
                VFILL((kt + 1) & 1, kt + 1);
                CP_COMMIT();
            }

            float s[8][4] = {};
            SCOMP3(kt & 1);
            SMASK(kt);

            #pragma unroll
            for (int nt = 0; nt < 8; ++nt) {
                s[nt][0] = __expf(s[nt][0]) * li0;
                s[nt][1] = __expf(s[nt][1]) * li0;
                s[nt][2] = __expf(s[nt][2]) * li1;
                s[nt][3] = __expf(s[nt][3]) * li1;
            }

            {
                float* pr0 = Pout + ((size_t)bh * 1024 + gr0) * 1024 + kt * 64 + (lane & 3) * 2;
                float* pr1 = pr0 + 8 * 1024;
                #pragma unroll
                for (int nt = 0; nt < 8; ++nt) {
                    *(float2*)&pr0[nt * 8] = make_float2(s[nt][0], s[nt][1]);
                    *(float2*)&pr1[nt * 8] = make_float2(s[nt][2], s[nt][3]);
                }
            }

            const uint32_t vhb = smb + AT_V_H(kt & 1);
            #pragma unroll
            for (int ksv = 0; ksv < 4; ++ksv) {
                uint32_t ah[4];
                ah[0] = pack_h2(s[2*ksv][0],   s[2*ksv][1]);
                ah[1] = pack_h2(s[2*ksv][2],   s[2*ksv][3]);
                ah[2] = pack_h2(s[2*ksv+1][0], s[2*ksv+1][1]);
                ah[3] = pack_h2(s[2*ksv+1][2], s[2*ksv+1][3]);
                uint32_t vrow = (uint32_t)((ksv * 16 + (lane & 15)) * 144);
                #pragma unroll
                for (int ntv = 0; ntv < 8; ++ntv) {
                    uint32_t vb0, vb1;
                    ldsm_x2t(vb0, vb1, vhb + vrow + ntv * 16);
                    mma_f16(o[ntv], ah[0], ah[1], ah[2], ah[3], vb0, vb1);
                }
            }
        }

        // zero-fill P tail (cols >= ncol)
        {
            float4 z = make_float4(0.f, 0.f, 0.f, 0.f);
            float* base0 = Pout + ((size_t)bh * 1024 + gr0) * 1024;
            float* base1 = base0 + 8 * 1024;
            for (int col = ncol + (lane & 3) * 4; col < 1024; col += 16) {
                *(float4*)&base0[col] = z;
                *(float4*)&base1[col] = z;
            }
        }

        // O epilogue -> qkvh (fp16); p already includes 1/l
        {
            const int b = bh >> 4, h = bh & 15;
            size_t i0 = ((size_t)(b * 1024 + gr0)) * 1024 + h * 64 + (lane & 3) * 2;
            size_t i1 = i0 + 8 * 1024;
            #pragma unroll
            for (int ntv = 0; ntv < 8; ++ntv) {
                *(uint32_t*)&qkvh[i0 + ntv * 8] = pack_h2(o[ntv][0], o[ntv][1]);
                *(uint32_t*)&qkvh[i1 + ntv * 8] = pack_h2(o[ntv][2], o[ntv][3]);
            }
        }
    }
    #undef KFILL
    #undef VFILL
    #undef SCOMP1
    #undef SCOMP3
    #undef SMASK
}

// ---------------------------------------------------------------------------
// LayerNorm (unchanged R9)
// ---------------------------------------------------------------------------
__global__ void __launch_bounds__(256)
ln_kernel(const float* __restrict__ gamma,
          const float* __restrict__ beta,
          float* __restrict__ out)
{
    const int row = blockIdx.x;
    const int tid = threadIdx.x;
    const int c4  = tid * 4;
    const int hf  = tid >> 7;
    const int wrp = tid >> 5;

    float4 v = *(const float4*)&g_tmp[(size_t)row * 1024 + c4];
    float s  = v.x + v.y + v.z + v.w;
    float sq = v.x*v.x + v.y*v.y + v.z*v.z + v.w*v.w;
    #pragma unroll
    for (int off = 16; off > 0; off >>= 1) {
        s  += __shfl_xor_sync(0xffffffffu, s,  off);
        sq += __shfl_xor_sync(0xffffffffu, sq, off);
    }
    __shared__ float ss[8], sqq[8];
    if ((tid & 31) == 0) { ss[wrp] = s; sqq[wrp] = sq; }
    __syncthreads();
    float tot = 0.f, totq = 0.f;
    #pragma unroll
    for (int w = 0; w < 4; ++w) { tot += ss[hf * 4 + w]; totq += sqq[hf * 4 + w]; }

    float mu  = tot * (1.0f / 512.0f);
    float var = totq * (1.0f / 512.0f) - mu * mu;
    float rstd = rsqrtf(var + 1e-5f);

    int gc = c4 & 511;
    float4 g = *(const float4*)&gamma[gc];
    float4 b = *(const float4*)&beta[gc];
    float4 r;
    r.x = (v.x - mu) * rstd * g.x + b.x;
    r.y = (v.y - mu) * rstd * g.y + b.y;
    r.z = (v.z - mu) * rstd * g.z + b.z;
    r.w = (v.w - mu) * rstd * g.w + b.w;
    *(float4*)&out[(size_t)row * 1024 + c4] = r;
}

// ---------------------------------------------------------------------------
extern "C" void kernel_launch(void* const* d_in, const int* in_sizes, int n_in,
                              void* d_out, int out_size)
{
    const float* inQ  = (const float*)d_in[0];
    const float* inK  = (const float*)d_in[1];
    const float* inV  = (const float*)d_in[2];
    const float* WQ1  = (const float*)d_in[4];
    const float* WK1  = (const float*)d_in[5];
    const float* WV1  = (const float*)d_in[6];
    const float* WV2  = (const float*)d_in[9];
    const float* Wfc1 = (const float*)d_in[10];
    const float* Wfc2 = (const float*)d_in[11];
    const float* ln_g = (const float*)d_in[12];
    const float* ln_b = (const float*)d_in[13];

    float* out  = (float*)d_out;
    float* Pout = out + (size_t)B_ * S_ * D_;

    cudaFuncSetAttribute(attn_flash, cudaFuncAttributeMaxDynamicSharedMemorySize,
                         ATTN_SMEM);
    cudaFuncSetAttribute(mma_gemm<2>, cudaFuncAttributeMaxDynamicSharedMemorySize,
                         GEMM_SMEM);
    cudaFuncSetAttribute(mma_gemm<1>, cudaFuncAttributeMaxDynamicSharedMemorySize,
                         GEMM_SMEM);

    // 0) split GEMM operands to fp16 (Q,K hi+lo; V,W hi)
    presplit<<<dim3(256, 9), 256>>>(inQ, inK, inV, WQ1, WK1, WV1, WV2, Wfc1, Wfc2);
    // 1) projections: Q1,K1 (2-term), V1,V2 (1-term)
    mma_gemm<2><<<dim3(32, 4, 2), 512, GEMM_SMEM>>>(inQ, 0);
    mma_gemm<1><<<dim3(32, 4, 2), 512, GEMM_SMEM>>>(inQ, 2);
    // 2) flash attention, paired slabs: single balanced wave
    attn_flash<<<dim3(64, 8), 128, ATTN_SMEM>>>(Pout);
    // 3) FC + residual (1-term)
    mma_gemm<1><<<dim3(32, 4, 2), 512, GEMM_SMEM>>>(inQ, 4);
    // 4) LayerNorm -> final output
    ln_kernel<<<dim3(B_ * S_), 256>>>(ln_g, ln_b, out);
}

// round 11
// speedup vs baseline: 1.0331x; 1.0331x over previous
#include <cuda_runtime.h>
#include <cuda_fp16.h>
#include <math.h>
#include <stdint.h>

// Problem constants
#define B_  4
#define S_  1024
#define D_  1024
#define H_  16
#define DKH_ 32
#define DV_  64

// ---------------------------------------------------------------------------
// Scratch (device globals; no allocations allowed)
// ---------------------------------------------------------------------------
__device__ __half pQh[4096*512],  pQl[4096*512];
__device__ __half pKh[4096*512],  pKl[4096*512];
__device__ __half pVh_[4096*1024];
__device__ __half pWh[6*512*512];
__device__ __half g_Q1h[64*1024*32], g_Q1l[64*1024*32];  // pre-scaled
__device__ __half g_K1h[64*1024*32], g_K1l[64*1024*32];
__device__ __half g_Vh [64*1024*64];
__device__ __half qkvh[4096*1024];
__device__ float g_tmp[B_*S_*D_];

// ===========================================================================
// helpers
// ===========================================================================
__device__ __forceinline__ uint32_t smem_u32(const void* p) {
    uint32_t a;
    asm("{ .reg .u64 t; cvta.to.shared.u64 t, %1; cvt.u32.u64 %0, t; }"
        : "=r"(a) : "l"(p));
    return a;
}
__device__ __forceinline__ void ldsm_x4(uint32_t& r0, uint32_t& r1,
                                        uint32_t& r2, uint32_t& r3, uint32_t addr) {
    asm volatile("ldmatrix.sync.aligned.m8n8.x4.shared.b16 {%0,%1,%2,%3}, [%4];"
                 : "=r"(r0), "=r"(r1), "=r"(r2), "=r"(r3) : "r"(addr));
}
__device__ __forceinline__ void ldsm_x2(uint32_t& r0, uint32_t& r1, uint32_t addr) {
    asm volatile("ldmatrix.sync.aligned.m8n8.x2.shared.b16 {%0,%1}, [%2];"
                 : "=r"(r0), "=r"(r1) : "r"(addr));
}
__device__ __forceinline__ void ldsm_x2t(uint32_t& r0, uint32_t& r1, uint32_t addr) {
    asm volatile("ldmatrix.sync.aligned.m8n8.x2.trans.shared.b16 {%0,%1}, [%2];"
                 : "=r"(r0), "=r"(r1) : "r"(addr));
}
__device__ __forceinline__ void mma_f16(float* c, uint32_t a0, uint32_t a1,
                                        uint32_t a2, uint32_t a3,
                                        uint32_t b0, uint32_t b1) {
    asm volatile("mma.sync.aligned.m16n8k16.row.col.f32.f16.f16.f32 "
                 "{%0,%1,%2,%3}, {%4,%5,%6,%7}, {%8,%9}, {%0,%1,%2,%3};"
                 : "+f"(c[0]), "+f"(c[1]), "+f"(c[2]), "+f"(c[3])
                 : "r"(a0), "r"(a1), "r"(a2), "r"(a3), "r"(b0), "r"(b1));
}
__device__ __forceinline__ uint32_t pack_h2(float x, float y) {
    __half2 t = __floats2half2_rn(x, y);
    return *reinterpret_cast<uint32_t*>(&t);
}
__device__ __forceinline__ void split2h(float x, float y, uint32_t& hi, uint32_t& lo) {
    __half hx = __float2half_rn(x);
    __half hy = __float2half_rn(y);
    __half2 h; h.x = hx; h.y = hy;
    hi = *reinterpret_cast<uint32_t*>(&h);
    lo = pack_h2(x - __half2float(hx), y - __half2float(hy));
}
__device__ __forceinline__ void cp16(uint32_t dst, const void* src) {
    asm volatile("cp.async.cg.shared.global [%0], [%1], 16;"
                 :: "r"(dst), "l"(src));
}
#define CP_COMMIT()  asm volatile("cp.async.commit_group;" ::: "memory")
#define CP_WAIT(N)   asm volatile("cp.async.wait_group %0;" :: "n"(N) : "memory")

// ===========================================================================
// presplit: fp32 -> fp16 for all GEMM operands.
// ===========================================================================
__global__ void __launch_bounds__(256)
presplit(const float* __restrict__ inQ, const float* __restrict__ inK,
         const float* __restrict__ inV,
         const float* __restrict__ W0, const float* __restrict__ W1,
         const float* __restrict__ W2, const float* __restrict__ W3,
         const float* __restrict__ W4, const float* __restrict__ W5)
{
    const int seg = blockIdx.y;
    const int gid = blockIdx.x * 256 + threadIdx.x;
    const int stride4 = gridDim.x * 256 * 4;

    if (seg < 2) {
        const float* s = seg ? inK : inQ;
        __half* dh = seg ? pKh : pQh;
        __half* dl = seg ? pKl : pQl;
        for (int i = gid * 4; i < 4096 * 512; i += stride4) {
            int row = i >> 9, col = i & 511;
            float4 v = *(const float4*)&s[(size_t)row * 1024 + col];
            uint32_t h0, l0, h1, l1;
            split2h(v.x, v.y, h0, l0); split2h(v.z, v.w, h1, l1);
            *(uint2*)&dh[i] = make_uint2(h0, h1);
            *(uint2*)&dl[i] = make_uint2(l0, l1);
        }
    } else if (seg == 2) {
        for (int i = gid * 4; i < 4096 * 1024; i += stride4) {
            float4 v = *(const float4*)&inV[i];
            *(uint2*)&pVh_[i] = make_uint2(pack_h2(v.x, v.y), pack_h2(v.z, v.w));
        }
    } else {
        const int w = seg - 3;
        const float* s = (w == 0) ? W0 : (w == 1) ? W1 : (w == 2) ? W2
                       : (w == 3) ? W3 : (w == 4) ? W4 : W5;
        __half* dh = pWh + (size_t)w * 262144;
        for (int i = gid * 4; i < 262144; i += stride4) {
            float4 v = *(const float4*)&s[i];
            *(uint2*)&dh[i] = make_uint2(pack_h2(v.x, v.y), pack_h2(v.z, v.w));
        }
    }
}

// ===========================================================================
// HMMA GEMM (unchanged): 512 threads, 128x128 tile, 3-stage pipeline.
//   NT=2: (Ah + Al) x Wh   (modes 0,1: Q1,K1 proj)
//   NT=1:  Ah x Wh         (modes 2,3: V proj; 4,5: FC + residual)
// ===========================================================================
#define APITCH 80
#define BPITCH 272
#define ST_SZ  29184u
#define ST_AH(s) ((s) * ST_SZ)
#define ST_AL(s) ((s) * ST_SZ + 10240u)
#define ST_BH(s) ((s) * ST_SZ + 20480u)
#define GEMM_SMEM (3 * 29184)

template<int NT>
__global__ void __launch_bounds__(512, 1)
mma_gemm(const float* __restrict__ inQ, int mode_base)
{
    extern __shared__ unsigned char sm[];
    const uint32_t smb = smem_u32(sm);

    const int mode = mode_base + blockIdx.z;
    const __half *pAh, *pAl;
    int apitch, aoff;
    switch (mode) {
        case 0: pAh = pQh;  pAl = pQl;  apitch = 512;  aoff = 0;   break;
        case 1: pAh = pKh;  pAl = pKl;  apitch = 512;  aoff = 0;   break;
        case 2: pAh = pVh_; pAl = pVh_; apitch = 1024; aoff = 0;   break;
        case 3: pAh = pVh_; pAl = pVh_; apitch = 1024; aoff = 512; break;
        case 4: pAh = qkvh; pAl = qkvh; apitch = 1024; aoff = 0;   break;
        default:pAh = qkvh; pAl = qkvh; apitch = 1024; aoff = 512; break;
    }
    const __half* wh = pWh + (size_t)mode * 262144;

    const int m0 = blockIdx.x * 128;
    const int n0 = blockIdx.y * 128;
    const int tid  = threadIdx.x;
    const int wid  = tid >> 5;
    const int lane = tid & 31;
    const int wy = wid >> 2;
    const int wx = wid & 3;

    const int ar = tid >> 2, aseg = tid & 3;
    const int br = tid >> 4, bseg = tid & 15;

    #define GFILL(st, k0)                                                         \
    {                                                                             \
        const __half* sha = pAh + (size_t)(m0 + ar) * apitch + aoff + (k0) + aseg * 8; \
        uint32_t da = (uint32_t)(ar * APITCH + aseg * 16);                        \
        cp16(smb + ST_AH(st) + da, sha);                                          \
        if (NT == 2) {                                                            \
            const __half* sla = pAl + (size_t)(m0 + ar) * apitch + aoff + (k0) + aseg * 8; \
            cp16(smb + ST_AL(st) + da, sla);                                      \
        }                                                                         \
        const __half* shb = wh + (size_t)((k0) + br) * 512 + n0 + bseg * 8;       \
        uint32_t db = (uint32_t)(br * BPITCH + bseg * 16);                        \
        cp16(smb + ST_BH(st) + db, shb);                                          \
        CP_COMMIT();                                                              \
    }

    float c[2][4][4] = {};

    const int a_row_in_tile = lane & 15;
    const int a_kseg        = (lane >> 4) & 1;
    const int b_krow        = (lane & 7) + ((lane >> 3) & 1) * 8;

    GFILL(0, 0);
    GFILL(1, 32);

    for (int chunk = 0; chunk < 16; ++chunk) {
        if (chunk + 1 < 16) { CP_WAIT(1); } else { CP_WAIT(0); }
        __syncthreads();
        if (chunk + 2 < 16) {
            int st = (chunk + 2) % 3;
            GFILL(st, (chunk + 2) * 32);
        }
        const int cs = chunk % 3;
        const uint32_t ahb = smb + ST_AH(cs);
        const uint32_t alb = smb + ST_AL(cs);
        const uint32_t bhb = smb + ST_BH(cs);

        #pragma unroll
        for (int ks = 0; ks < 2; ++ks) {
            uint32_t ahf[2][4], alf[2][4];
            #pragma unroll
            for (int mt = 0; mt < 2; ++mt) {
                int row = wy * 32 + mt * 16 + a_row_in_tile;
                uint32_t aoffb = (uint32_t)(row * APITCH + ks * 32 + a_kseg * 16);
                ldsm_x4(ahf[mt][0], ahf[mt][1], ahf[mt][2], ahf[mt][3], ahb + aoffb);
                if (NT == 2)
                    ldsm_x4(alf[mt][0], alf[mt][1], alf[mt][2], alf[mt][3], alb + aoffb);
            }
            uint32_t bhf[4][2];
            #pragma unroll
            for (int nt = 0; nt < 4; ++nt) {
                uint32_t boffb = (uint32_t)((ks * 16 + b_krow) * BPITCH
                                            + (wx * 32 + nt * 8) * 2);
                ldsm_x2t(bhf[nt][0], bhf[nt][1], bhb + boffb);
            }
            #pragma unroll
            for (int mt = 0; mt < 2; ++mt) {
                #pragma unroll
                for (int nt = 0; nt < 4; ++nt) {
                    mma_f16(c[mt][nt], ahf[mt][0], ahf[mt][1], ahf[mt][2], ahf[mt][3],
                            bhf[nt][0], bhf[nt][1]);
                    if (NT == 2)
                        mma_f16(c[mt][nt], alf[mt][0], alf[mt][1], alf[mt][2], alf[mt][3],
                                bhf[nt][0], bhf[nt][1]);
                }
            }
        }
    }

    // ---- epilogue ----
    const int gid = lane >> 2;
    const int tig = lane & 3;

    #pragma unroll
    for (int mt = 0; mt < 2; ++mt) {
        int row = m0 + wy * 32 + mt * 16 + gid;
        int b = row >> 10, s = row & 1023;
        #pragma unroll
        for (int nt = 0; nt < 4; ++nt) {
            int col = n0 + wx * 32 + nt * 8 + tig * 2;
            float2 v01 = make_float2(c[mt][nt][0], c[mt][nt][1]);
            float2 v23 = make_float2(c[mt][nt][2], c[mt][nt][3]);
            if (mode <= 1) {
                int h = col >> 5, d = col & 31;
                __half* dh = (mode == 0) ? g_Q1h : g_K1h;
                __half* dl = (mode == 0) ? g_Q1l : g_K1l;
                float sc = (mode == 0) ? 0.17677669529663688f : 1.0f;
                size_t base = ((size_t)(b * 16 + h) * 1024) * 32 + d;
                uint32_t hi, lo;
                split2h(v01.x * sc, v01.y * sc, hi, lo);
                *(uint32_t*)&dh[base + (size_t)s * 32] = hi;
                *(uint32_t*)&dl[base + (size_t)s * 32] = lo;
                split2h(v23.x * sc, v23.y * sc, hi, lo);
                *(uint32_t*)&dh[base + (size_t)(s + 8) * 32] = hi;
                *(uint32_t*)&dl[base + (size_t)(s + 8) * 32] = lo;
            } else if (mode <= 3) {
                int h = col >> 5, d = (col & 31) + (mode == 3 ? 32 : 0);
                size_t base = ((size_t)(b * 16 + h) * 1024) * 64 + d;
                *(uint32_t*)&g_Vh[base + (size_t)s * 64]       = pack_h2(v01.x, v01.y);
                *(uint32_t*)&g_Vh[base + (size_t)(s + 8) * 64] = pack_h2(v23.x, v23.y);
            } else {
                int half = mode - 4;
                size_t idx0 = (size_t)row * 1024 + half * 512 + col;
                size_t idx1 = idx0 + 8 * 1024;
                float2 r0 = *(const float2*)&inQ[idx0];
                float2 r1 = *(const float2*)&inQ[idx1];
                *(float2*)&g_tmp[idx0] = make_float2(v01.x + r0.x, v01.y + r0.y);
                *(float2*)&g_tmp[idx1] = make_float2(v23.x + r1.x, v23.y + r1.y);
            }
        }
    }
    #undef GFILL
}

// ===========================================================================
// Flash attention (R9 grid: 1 slab/CTA, 1024 CTAs, LPT) with R10's 1-term
// pass-1. Pass1: QK 1-term -> l. Pass2: QK 3-term -> P write + PV 1-term.
// ===========================================================================
#define AT_K_H(buf) ((buf) * 5120u)
#define AT_K_L(buf) (10240u + (buf) * 5120u)
#define AT_V_H(buf) (20480u + (buf) * 9216u)
#define AT_Q_H 20480u
#define AT_Q_L 25600u
#define ATTN_SMEM 38912

__global__ void __launch_bounds__(128, 4)
attn_flash(float* __restrict__ Pout)
{
    extern __shared__ unsigned char sm[];
    const uint32_t smb = smem_u32(sm);

    const int bh = blockIdx.x;
    const int qs = 15 - (int)blockIdx.y;   // LPT: heavy slabs first
    const int q0 = qs * 64;
    const int nkt = qs + 1;
    const int ncol = nkt * 64;
    const int tid = threadIdx.x, wid = tid >> 5, lane = tid & 31;

    const int frow = tid >> 1;
    const int fs2  = (tid & 1) * 2;
    const int fs4  = (tid & 1) * 4;

#define KFILL(buf, kt, withlo)                                                    \
    {                                                                             \
        const __half* sh_ = g_K1h + ((size_t)bh*1024 + (size_t)(kt)*64 + frow)*32 + fs2*8; \
        uint32_t d_ = (uint32_t)(frow * 80 + fs2 * 16);                           \
        cp16(smb + AT_K_H(buf) + d_,      sh_);                                   \
        cp16(smb + AT_K_H(buf) + d_ + 16, sh_ + 8);                               \
        if (withlo) {                                                             \
            const __half* sl_ = g_K1l + ((size_t)bh*1024 + (size_t)(kt)*64 + frow)*32 + fs2*8; \
            cp16(smb + AT_K_L(buf) + d_,      sl_);                               \
            cp16(smb + AT_K_L(buf) + d_ + 16, sl_ + 8);                           \
        }                                                                         \
    }
#define VFILL(buf, kt)                                                            \
    {                                                                             \
        const __half* sh_ = g_Vh + ((size_t)bh*1024 + (size_t)(kt)*64 + frow)*64 + fs4*8; \
        uint32_t d_ = (uint32_t)(frow * 144 + fs4 * 16);                          \
        _Pragma("unroll")                                                         \
        for (int u_ = 0; u_ < 4; ++u_)                                            \
            cp16(smb + AT_V_H(buf) + d_ + u_*16, sh_ + u_*8);                     \
    }

    KFILL(0, 0, false); CP_COMMIT();

    // stage Q slab (64 x 32 fp16 hi/lo)
    {
        const __half* qh = g_Q1h + ((size_t)bh*1024 + q0 + frow)*32 + fs2*8;
        const __half* ql = g_Q1l + ((size_t)bh*1024 + q0 + frow)*32 + fs2*8;
        uint32_t d = (uint32_t)(frow * 80 + fs2 * 16);
        *(uint4*)(sm + AT_Q_H + d)      = *(const uint4*)qh;
        *(uint4*)(sm + AT_Q_H + d + 16) = *(const uint4*)(qh + 8);
        *(uint4*)(sm + AT_Q_L + d)      = *(const uint4*)ql;
        *(uint4*)(sm + AT_Q_L + d + 16) = *(const uint4*)(ql + 8);
    }
    __syncthreads();

    uint32_t qfh[2][4], qfl[2][4];
    #pragma unroll
    for (int ks = 0; ks < 2; ++ks) {
        uint32_t off = (uint32_t)((wid * 16 + (lane & 15)) * 80
                                  + ks * 32 + ((lane >> 4) & 1) * 16);
        ldsm_x4(qfh[ks][0], qfh[ks][1], qfh[ks][2], qfh[ks][3], smb + AT_Q_H + off);
        ldsm_x4(qfl[ks][0], qfl[ks][1], qfl[ks][2], qfl[ks][3], smb + AT_Q_L + off);
    }

    const int gr0 = q0 + wid * 16 + (lane >> 2);

    #define SCOMP1(buf)                                                           \
    {                                                                             \
        const uint32_t khb = smb + AT_K_H(buf);                                   \
        _Pragma("unroll")                                                         \
        for (int ks = 0; ks < 2; ++ks) {                                          \
            _Pragma("unroll")                                                     \
            for (int nt = 0; nt < 8; ++nt) {                                      \
                uint32_t boff = (uint32_t)((nt * 8 + (lane & 7)) * 80             \
                                           + ks * 32 + ((lane >> 3) & 1) * 16);   \
                uint32_t b0, b1;                                                  \
                ldsm_x2(b0, b1, khb + boff);                                      \
                mma_f16(s[nt], qfh[ks][0], qfh[ks][1], qfh[ks][2], qfh[ks][3], b0, b1); \
            }                                                                     \
        }                                                                         \
    }
    #define SCOMP3(buf)                                                           \
    {                                                                             \
        const uint32_t khb = smb + AT_K_H(buf);                                   \
        const uint32_t klb = smb + AT_K_L(buf);                                   \
        _Pragma("unroll")                                                         \
        for (int ks = 0; ks < 2; ++ks) {                                          \
            _Pragma("unroll")                                                     \
            for (int nt = 0; nt < 8; ++nt) {                                      \
                uint32_t boff = (uint32_t)((nt * 8 + (lane & 7)) * 80             \
                                           + ks * 32 + ((lane >> 3) & 1) * 16);   \
                uint32_t b0, b1, d0, d1;                                          \
                ldsm_x2(b0, b1, khb + boff);                                      \
                ldsm_x2(d0, d1, klb + boff);                                      \
                mma_f16(s[nt], qfh[ks][0], qfh[ks][1], qfh[ks][2], qfh[ks][3], b0, b1); \
                mma_f16(s[nt], qfh[ks][0], qfh[ks][1], qfh[ks][2], qfh[ks][3], d0, d1); \
                mma_f16(s[nt], qfl[ks][0], qfl[ks][1], qfl[ks][2], qfl[ks][3], b0, b1); \
            }                                                                     \
        }                                                                         \
    }
    #define SMASK(kt)                                                             \
    if ((kt) == nkt - 1) {                                                        \
        int cb = (kt) * 64 + (lane & 3) * 2;                                      \
        _Pragma("unroll")                                                         \
        for (int nt = 0; nt < 8; ++nt) {                                          \
            int c0 = cb + nt * 8;                                                 \
            if (c0     > gr0)     s[nt][0] = -1e30f;                              \
            if (c0 + 1 > gr0)     s[nt][1] = -1e30f;                              \
            if (c0     > gr0 + 8) s[nt][2] = -1e30f;                              \
            if (c0 + 1 > gr0 + 8) s[nt][3] = -1e30f;                              \
        }                                                                         \
    }

    // ================= Pass 1: l = sum exp(s), 1-term QK =================
    float l0 = 0.f, l1 = 0.f;

    for (int kt = 0; kt < nkt; ++kt) {
        CP_WAIT(0);
        __syncthreads();
        if (kt + 1 < nkt) { KFILL((kt + 1) & 1, kt + 1, false); CP_COMMIT(); }

        float s[8][4] = {};
        SCOMP1(kt & 1);
        SMASK(kt);

        float a0 = 0.f, a1 = 0.f;
        #pragma unroll
        for (int nt = 0; nt < 8; ++nt) {
            a0 += __expf(s[nt][0]) + __expf(s[nt][1]);
            a1 += __expf(s[nt][2]) + __expf(s[nt][3]);
        }
        a0 += __shfl_xor_sync(0xffffffffu, a0, 1);
        a0 += __shfl_xor_sync(0xffffffffu, a0, 2);
        a1 += __shfl_xor_sync(0xffffffffu, a1, 1);
        a1 += __shfl_xor_sync(0xffffffffu, a1, 2);
        l0 += a0;
        l1 += a1;
    }
    const float li0 = 1.0f / l0, li1 = 1.0f / l1;

    // ================= Pass 2: P write + O = P @ V =================
    __syncthreads();
    KFILL(0, 0, true); VFILL(0, 0); CP_COMMIT();

    float o[8][4] = {};

    for (int kt = 0; kt < nkt; ++kt) {
        CP_WAIT(0);
        __syncthreads();
        if (kt + 1 < nkt) {
            KFILL((kt + 1) & 1, kt + 1, true);
            VFILL((kt + 1) & 1, kt + 1);
            CP_COMMIT();
        }

        float s[8][4] = {};
        SCOMP3(kt & 1);
        SMASK(kt);

        #pragma unroll
        for (int nt = 0; nt < 8; ++nt) {
            s[nt][0] = __expf(s[nt][0]) * li0;
            s[nt][1] = __expf(s[nt][1]) * li0;
            s[nt][2] = __expf(s[nt][2]) * li1;
            s[nt][3] = __expf(s[nt][3]) * li1;
        }

        {
            float* pr0 = Pout + ((size_t)bh * 1024 + gr0) * 1024 + kt * 64 + (lane & 3) * 2;
            float* pr1 = pr0 + 8 * 1024;
            #pragma unroll
            for (int nt = 0; nt < 8; ++nt) {
                *(float2*)&pr0[nt * 8] = make_float2(s[nt][0], s[nt][1]);
                *(float2*)&pr1[nt * 8] = make_float2(s[nt][2], s[nt][3]);
            }
        }

        const uint32_t vhb = smb + AT_V_H(kt & 1);
        #pragma unroll
        for (int ksv = 0; ksv < 4; ++ksv) {
            uint32_t ah[4];
            ah[0] = pack_h2(s[2*ksv][0],   s[2*ksv][1]);
            ah[1] = pack_h2(s[2*ksv][2],   s[2*ksv][3]);
            ah[2] = pack_h2(s[2*ksv+1][0], s[2*ksv+1][1]);
            ah[3] = pack_h2(s[2*ksv+1][2], s[2*ksv+1][3]);
            uint32_t vrow = (uint32_t)((ksv * 16 + (lane & 15)) * 144);
            #pragma unroll
            for (int ntv = 0; ntv < 8; ++ntv) {
                uint32_t vb0, vb1;
                ldsm_x2t(vb0, vb1, vhb + vrow + ntv * 16);
                mma_f16(o[ntv], ah[0], ah[1], ah[2], ah[3], vb0, vb1);
            }
        }
    }

    // zero-fill P tail (cols >= ncol)
    {
        float4 z = make_float4(0.f, 0.f, 0.f, 0.f);
        float* base0 = Pout + ((size_t)bh * 1024 + gr0) * 1024;
        float* base1 = base0 + 8 * 1024;
        for (int col = ncol + (lane & 3) * 4; col < 1024; col += 16) {
            *(float4*)&base0[col] = z;
            *(float4*)&base1[col] = z;
        }
    }

    // O epilogue -> qkvh (fp16); p already includes 1/l
    {
        const int b = bh >> 4, h = bh & 15;
        size_t i0 = ((size_t)(b * 1024 + gr0)) * 1024 + h * 64 + (lane & 3) * 2;
        size_t i1 = i0 + 8 * 1024;
        #pragma unroll
        for (int ntv = 0; ntv < 8; ++ntv) {
            *(uint32_t*)&qkvh[i0 + ntv * 8] = pack_h2(o[ntv][0], o[ntv][1]);
            *(uint32_t*)&qkvh[i1 + ntv * 8] = pack_h2(o[ntv][2], o[ntv][3]);
        }
    }
    #undef KFILL
    #undef VFILL
    #undef SCOMP1
    #undef SCOMP3
    #undef SMASK
}

// ---------------------------------------------------------------------------
// LayerNorm (unchanged)
// ---------------------------------------------------------------------------
__global__ void __launch_bounds__(256)
ln_kernel(const float* __restrict__ gamma,
          const float* __restrict__ beta,
          float* __restrict__ out)
{
    const int row = blockIdx.x;
    const int tid = threadIdx.x;
    const int c4  = tid * 4;
    const int hf  = tid >> 7;
    const int wrp = tid >> 5;

    float4 v = *(const float4*)&g_tmp[(size_t)row * 1024 + c4];
    float s  = v.x + v.y + v.z + v.w;
    float sq = v.x*v.x + v.y*v.y + v.z*v.z + v.w*v.w;
    #pragma unroll
    for (int off = 16; off > 0; off >>= 1) {
        s  += __shfl_xor_sync(0xffffffffu, s,  off);
        sq += __shfl_xor_sync(0xffffffffu, sq, off);
    }
    __shared__ float ss[8], sqq[8];
    if ((tid & 31) == 0) { ss[wrp] = s; sqq[wrp] = sq; }
    __syncthreads();
    float tot = 0.f, totq = 0.f;
    #pragma unroll
    for (int w = 0; w < 4; ++w) { tot += ss[hf * 4 + w]; totq += sqq[hf * 4 + w]; }

    float mu  = tot * (1.0f / 512.0f);
    float var = totq * (1.0f / 512.0f) - mu * mu;
    float rstd = rsqrtf(var + 1e-5f);

    int gc = c4 & 511;
    float4 g = *(const float4*)&gamma[gc];
    float4 b = *(const float4*)&beta[gc];
    float4 r;
    r.x = (v.x - mu) * rstd * g.x + b.x;
    r.y = (v.y - mu) * rstd * g.y + b.y;
    r.z = (v.z - mu) * rstd * g.z + b.z;
    r.w = (v.w - mu) * rstd * g.w + b.w;
    *(float4*)&out[(size_t)row * 1024 + c4] = r;
}

// ---------------------------------------------------------------------------
extern "C" void kernel_launch(void* const* d_in, const int* in_sizes, int n_in,
                              void* d_out, int out_size)
{
    const float* inQ  = (const float*)d_in[0];
    const float* inK  = (const float*)d_in[1];
    const float* inV  = (const float*)d_in[2];
    const float* WQ1  = (const float*)d_in[4];
    const float* WK1  = (const float*)d_in[5];
    const float* WV1  = (const float*)d_in[6];
    const float* WV2  = (const float*)d_in[9];
    const float* Wfc1 = (const float*)d_in[10];
    const float* Wfc2 = (const float*)d_in[11];
    const float* ln_g = (const float*)d_in[12];
    const float* ln_b = (const float*)d_in[13];

    float* out  = (float*)d_out;
    float* Pout = out + (size_t)B_ * S_ * D_;

    cudaFuncSetAttribute(attn_flash, cudaFuncAttributeMaxDynamicSharedMemorySize,
                         ATTN_SMEM);
    cudaFuncSetAttribute(mma_gemm<2>, cudaFuncAttributeMaxDynamicSharedMemorySize,
                         GEMM_SMEM);
    cudaFuncSetAttribute(mma_gemm<1>, cudaFuncAttributeMaxDynamicSharedMemorySize,
                         GEMM_SMEM);

    // 0) split GEMM operands to fp16 (Q,K hi+lo; V,W hi)
    presplit<<<dim3(256, 9), 256>>>(inQ, inK, inV, WQ1, WK1, WV1, WV2, Wfc1, Wfc2);
    // 1) projections: Q1,K1 (2-term), V1,V2 (1-term)
    mma_gemm<2><<<dim3(32, 4, 2), 512, GEMM_SMEM>>>(inQ, 0);
    mma_gemm<1><<<dim3(32, 4, 2), 512, GEMM_SMEM>>>(inQ, 2);
    // 2) flash attention (1 slab/CTA, LPT), 1-term pass-1
    attn_flash<<<dim3(64, 16), 128, ATTN_SMEM>>>(Pout);
    // 3) FC + residual (1-term)
    mma_gemm<1><<<dim3(32, 4, 2), 512, GEMM_SMEM>>>(inQ, 4);
    // 4) LayerNorm -> final output
    ln_kernel<<<dim3(B_ * S_), 256>>>(ln_g, ln_b, out);
}

// round 12
// speedup vs baseline: 1.0513x; 1.0176x over previous
#include <cuda_runtime.h>
#include <cuda_fp16.h>
#include <math.h>
#include <stdint.h>

// Problem constants
#define B_  4
#define S_  1024
#define D_  1024
#define H_  16
#define DKH_ 32
#define DV_  64

// ---------------------------------------------------------------------------
// Scratch (device globals; no allocations allowed)
// ---------------------------------------------------------------------------
__device__ __half pQh[4096*512],  pQl[4096*512];
__device__ __half pKh[4096*512],  pKl[4096*512];
__device__ __half pVh_[4096*1024];
__device__ __half pWh[6*512*512];
__device__ __half g_Q1h[64*1024*32], g_Q1l[64*1024*32];  // pre-scaled by log2e/sqrt(32)
__device__ __half g_K1h[64*1024*32], g_K1l[64*1024*32];
__device__ __half g_Vh [64*1024*64];
__device__ __half qkvh[4096*1024];
__device__ float g_tmp[B_*S_*D_];

// ===========================================================================
// helpers
// ===========================================================================
__device__ __forceinline__ uint32_t smem_u32(const void* p) {
    uint32_t a;
    asm("{ .reg .u64 t; cvta.to.shared.u64 t, %1; cvt.u32.u64 %0, t; }"
        : "=r"(a) : "l"(p));
    return a;
}
__device__ __forceinline__ void ldsm_x4(uint32_t& r0, uint32_t& r1,
                                        uint32_t& r2, uint32_t& r3, uint32_t addr) {
    asm volatile("ldmatrix.sync.aligned.m8n8.x4.shared.b16 {%0,%1,%2,%3}, [%4];"
                 : "=r"(r0), "=r"(r1), "=r"(r2), "=r"(r3) : "r"(addr));
}
__device__ __forceinline__ void ldsm_x4t(uint32_t& r0, uint32_t& r1,
                                         uint32_t& r2, uint32_t& r3, uint32_t addr) {
    asm volatile("ldmatrix.sync.aligned.m8n8.x4.trans.shared.b16 {%0,%1,%2,%3}, [%4];"
                 : "=r"(r0), "=r"(r1), "=r"(r2), "=r"(r3) : "r"(addr));
}
__device__ __forceinline__ void ldsm_x2t(uint32_t& r0, uint32_t& r1, uint32_t addr) {
    asm volatile("ldmatrix.sync.aligned.m8n8.x2.trans.shared.b16 {%0,%1}, [%2];"
                 : "=r"(r0), "=r"(r1) : "r"(addr));
}
__device__ __forceinline__ void mma_f16(float* c, uint32_t a0, uint32_t a1,
                                        uint32_t a2, uint32_t a3,
                                        uint32_t b0, uint32_t b1) {
    asm volatile("mma.sync.aligned.m16n8k16.row.col.f32.f16.f16.f32 "
                 "{%0,%1,%2,%3}, {%4,%5,%6,%7}, {%8,%9}, {%0,%1,%2,%3};"
                 : "+f"(c[0]), "+f"(c[1]), "+f"(c[2]), "+f"(c[3])
                 : "r"(a0), "r"(a1), "r"(a2), "r"(a3), "r"(b0), "r"(b1));
}
__device__ __forceinline__ float ex2f(float x) {
    float r;
    asm("ex2.approx.f32 %0, %1;" : "=f"(r) : "f"(x));
    return r;
}
__device__ __forceinline__ uint32_t pack_h2(float x, float y) {
    __half2 t = __floats2half2_rn(x, y);
    return *reinterpret_cast<uint32_t*>(&t);
}
__device__ __forceinline__ void split2h(float x, float y, uint32_t& hi, uint32_t& lo) {
    __half hx = __float2half_rn(x);
    __half hy = __float2half_rn(y);
    __half2 h; h.x = hx; h.y = hy;
    hi = *reinterpret_cast<uint32_t*>(&h);
    lo = pack_h2(x - __half2float(hx), y - __half2float(hy));
}
__device__ __forceinline__ void cp16(uint32_t dst, const void* src) {
    asm volatile("cp.async.cg.shared.global [%0], [%1], 16;"
                 :: "r"(dst), "l"(src));
}
#define CP_COMMIT()  asm volatile("cp.async.commit_group;" ::: "memory")
#define CP_WAIT(N)   asm volatile("cp.async.wait_group %0;" :: "n"(N) : "memory")

// ===========================================================================
// presplit: fp32 -> fp16 for all GEMM operands.
// ===========================================================================
__global__ void __launch_bounds__(256)
presplit(const float* __restrict__ inQ, const float* __restrict__ inK,
         const float* __restrict__ inV,
         const float* __restrict__ W0, const float* __restrict__ W1,
         const float* __restrict__ W2, const float* __restrict__ W3,
         const float* __restrict__ W4, const float* __restrict__ W5)
{
    const int seg = blockIdx.y;
    const int gid = blockIdx.x * 256 + threadIdx.x;
    const int stride4 = gridDim.x * 256 * 4;

    if (seg < 2) {
        const float* s = seg ? inK : inQ;
        __half* dh = seg ? pKh : pQh;
        __half* dl = seg ? pKl : pQl;
        for (int i = gid * 4; i < 4096 * 512; i += stride4) {
            int row = i >> 9, col = i & 511;
            float4 v = *(const float4*)&s[(size_t)row * 1024 + col];
            uint32_t h0, l0, h1, l1;
            split2h(v.x, v.y, h0, l0); split2h(v.z, v.w, h1, l1);
            *(uint2*)&dh[i] = make_uint2(h0, h1);
            *(uint2*)&dl[i] = make_uint2(l0, l1);
        }
    } else if (seg == 2) {
        for (int i = gid * 4; i < 4096 * 1024; i += stride4) {
            float4 v = *(const float4*)&inV[i];
            *(uint2*)&pVh_[i] = make_uint2(pack_h2(v.x, v.y), pack_h2(v.z, v.w));
        }
    } else {
        const int w = seg - 3;
        const float* s = (w == 0) ? W0 : (w == 1) ? W1 : (w == 2) ? W2
                       : (w == 3) ? W3 : (w == 4) ? W4 : W5;
        __half* dh = pWh + (size_t)w * 262144;
        for (int i = gid * 4; i < 262144; i += stride4) {
            float4 v = *(const float4*)&s[i];
            *(uint2*)&dh[i] = make_uint2(pack_h2(v.x, v.y), pack_h2(v.z, v.w));
        }
    }
}

// ===========================================================================
// HMMA GEMM (unchanged): 512 threads, 128x128 tile, 3-stage pipeline.
//   NT=2: (Ah + Al) x Wh   (modes 0,1: Q1,K1 proj)
//   NT=1:  Ah x Wh         (modes 2,3: V proj; 4,5: FC + residual)
// ===========================================================================
#define APITCH 80
#define BPITCH 272
#define ST_SZ  29184u
#define ST_AH(s) ((s) * ST_SZ)
#define ST_AL(s) ((s) * ST_SZ + 10240u)
#define ST_BH(s) ((s) * ST_SZ + 20480u)
#define GEMM_SMEM (3 * 29184)

template<int NT>
__global__ void __launch_bounds__(512, 1)
mma_gemm(const float* __restrict__ inQ, int mode_base)
{
    extern __shared__ unsigned char sm[];
    const uint32_t smb = smem_u32(sm);

    const int mode = mode_base + blockIdx.z;
    const __half *pAh, *pAl;
    int apitch, aoff;
    switch (mode) {
        case 0: pAh = pQh;  pAl = pQl;  apitch = 512;  aoff = 0;   break;
        case 1: pAh = pKh;  pAl = pKl;  apitch = 512;  aoff = 0;   break;
        case 2: pAh = pVh_; pAl = pVh_; apitch = 1024; aoff = 0;   break;
        case 3: pAh = pVh_; pAl = pVh_; apitch = 1024; aoff = 512; break;
        case 4: pAh = qkvh; pAl = qkvh; apitch = 1024; aoff = 0;   break;
        default:pAh = qkvh; pAl = qkvh; apitch = 1024; aoff = 512; break;
    }
    const __half* wh = pWh + (size_t)mode * 262144;

    const int m0 = blockIdx.x * 128;
    const int n0 = blockIdx.y * 128;
    const int tid  = threadIdx.x;
    const int wid  = tid >> 5;
    const int lane = tid & 31;
    const int wy = wid >> 2;
    const int wx = wid & 3;

    const int ar = tid >> 2, aseg = tid & 3;
    const int br = tid >> 4, bseg = tid & 15;

    #define GFILL(st, k0)                                                         \
    {                                                                             \
        const __half* sha = pAh + (size_t)(m0 + ar) * apitch + aoff + (k0) + aseg * 8; \
        uint32_t da = (uint32_t)(ar * APITCH + aseg * 16);                        \
        cp16(smb + ST_AH(st) + da, sha);                                          \
        if (NT == 2) {                                                            \
            const __half* sla = pAl + (size_t)(m0 + ar) * apitch + aoff + (k0) + aseg * 8; \
            cp16(smb + ST_AL(st) + da, sla);                                      \
        }                                                                         \
        const __half* shb = wh + (size_t)((k0) + br) * 512 + n0 + bseg * 8;       \
        uint32_t db = (uint32_t)(br * BPITCH + bseg * 16);                        \
        cp16(smb + ST_BH(st) + db, shb);                                          \
        CP_COMMIT();                                                              \
    }

    float c[2][4][4] = {};

    const int a_row_in_tile = lane & 15;
    const int a_kseg        = (lane >> 4) & 1;
    const int b_krow        = (lane & 7) + ((lane >> 3) & 1) * 8;

    GFILL(0, 0);
    GFILL(1, 32);

    for (int chunk = 0; chunk < 16; ++chunk) {
        if (chunk + 1 < 16) { CP_WAIT(1); } else { CP_WAIT(0); }
        __syncthreads();
        if (chunk + 2 < 16) {
            int st = (chunk + 2) % 3;
            GFILL(st, (chunk + 2) * 32);
        }
        const int cs = chunk % 3;
        const uint32_t ahb = smb + ST_AH(cs);
        const uint32_t alb = smb + ST_AL(cs);
        const uint32_t bhb = smb + ST_BH(cs);

        #pragma unroll
        for (int ks = 0; ks < 2; ++ks) {
            uint32_t ahf[2][4], alf[2][4];
            #pragma unroll
            for (int mt = 0; mt < 2; ++mt) {
                int row = wy * 32 + mt * 16 + a_row_in_tile;
                uint32_t aoffb = (uint32_t)(row * APITCH + ks * 32 + a_kseg * 16);
                ldsm_x4(ahf[mt][0], ahf[mt][1], ahf[mt][2], ahf[mt][3], ahb + aoffb);
                if (NT == 2)
                    ldsm_x4(alf[mt][0], alf[mt][1], alf[mt][2], alf[mt][3], alb + aoffb);
            }
            uint32_t bhf[4][2];
            #pragma unroll
            for (int nt = 0; nt < 4; ++nt) {
                uint32_t boffb = (uint32_t)((ks * 16 + b_krow) * BPITCH
                                            + (wx * 32 + nt * 8) * 2);
                ldsm_x2t(bhf[nt][0], bhf[nt][1], bhb + boffb);
            }
            #pragma unroll
            for (int mt = 0; mt < 2; ++mt) {
                #pragma unroll
                for (int nt = 0; nt < 4; ++nt) {
                    mma_f16(c[mt][nt], ahf[mt][0], ahf[mt][1], ahf[mt][2], ahf[mt][3],
                            bhf[nt][0], bhf[nt][1]);
                    if (NT == 2)
                        mma_f16(c[mt][nt], alf[mt][0], alf[mt][1], alf[mt][2], alf[mt][3],
                                bhf[nt][0], bhf[nt][1]);
                }
            }
        }
    }

    // ---- epilogue ----
    const int gid = lane >> 2;
    const int tig = lane & 3;

    #pragma unroll
    for (int mt = 0; mt < 2; ++mt) {
        int row = m0 + wy * 32 + mt * 16 + gid;
        int b = row >> 10, s = row & 1023;
        #pragma unroll
        for (int nt = 0; nt < 4; ++nt) {
            int col = n0 + wx * 32 + nt * 8 + tig * 2;
            float2 v01 = make_float2(c[mt][nt][0], c[mt][nt][1]);
            float2 v23 = make_float2(c[mt][nt][2], c[mt][nt][3]);
            if (mode <= 1) {
                int h = col >> 5, d = col & 31;
                __half* dh = (mode == 0) ? g_Q1h : g_K1h;
                __half* dl = (mode == 0) ? g_Q1l : g_K1l;
                // Q scale: log2(e)/sqrt(32) so softmax uses ex2 directly
                float sc = (mode == 0) ? 0.25503487350122697f : 1.0f;
                size_t base = ((size_t)(b * 16 + h) * 1024) * 32 + d;
                uint32_t hi, lo;
                split2h(v01.x * sc, v01.y * sc, hi, lo);
                *(uint32_t*)&dh[base + (size_t)s * 32] = hi;
                *(uint32_t*)&dl[base + (size_t)s * 32] = lo;
                split2h(v23.x * sc, v23.y * sc, hi, lo);
                *(uint32_t*)&dh[base + (size_t)(s + 8) * 32] = hi;
                *(uint32_t*)&dl[base + (size_t)(s + 8) * 32] = lo;
            } else if (mode <= 3) {
                int h = col >> 5, d = (col & 31) + (mode == 3 ? 32 : 0);
                size_t base = ((size_t)(b * 16 + h) * 1024) * 64 + d;
                *(uint32_t*)&g_Vh[base + (size_t)s * 64]       = pack_h2(v01.x, v01.y);
                *(uint32_t*)&g_Vh[base + (size_t)(s + 8) * 64] = pack_h2(v23.x, v23.y);
            } else {
                int half = mode - 4;
                size_t idx0 = (size_t)row * 1024 + half * 512 + col;
                size_t idx1 = idx0 + 8 * 1024;
                float2 r0 = *(const float2*)&inQ[idx0];
                float2 r1 = *(const float2*)&inQ[idx1];
                *(float2*)&g_tmp[idx0] = make_float2(v01.x + r0.x, v01.y + r0.y);
                *(float2*)&g_tmp[idx1] = make_float2(v23.x + r1.x, v23.y + r1.y);
            }
        }
    }
    #undef GFILL
}

// ===========================================================================
// Flash attention: 1 slab/CTA, 1024 CTAs, LPT. x4-merged ldsm, ex2 softmax.
// Pass1: QK 1-term -> l. Pass2: QK 3-term -> P write + PV 1-term.
// ===========================================================================
#define AT_K_H(buf) ((buf) * 5120u)
#define AT_K_L(buf) (10240u + (buf) * 5120u)
#define AT_V_H(buf) (20480u + (buf) * 9216u)
#define AT_Q_H 20480u
#define AT_Q_L 25600u
#define ATTN_SMEM 38912

__global__ void __launch_bounds__(128, 4)
attn_flash(float* __restrict__ Pout)
{
    extern __shared__ unsigned char sm[];
    const uint32_t smb = smem_u32(sm);

    const int bh = blockIdx.x;
    const int qs = 15 - (int)blockIdx.y;   // LPT: heavy slabs first
    const int q0 = qs * 64;
    const int nkt = qs + 1;
    const int ncol = nkt * 64;
    const int tid = threadIdx.x, wid = tid >> 5, lane = tid & 31;

    const int frow = tid >> 1;
    const int fs2  = (tid & 1) * 2;
    const int fs4  = (tid & 1) * 4;

#define KFILL(buf, kt, withlo)                                                    \
    {                                                                             \
        const __half* sh_ = g_K1h + ((size_t)bh*1024 + (size_t)(kt)*64 + frow)*32 + fs2*8; \
        uint32_t d_ = (uint32_t)(frow * 80 + fs2 * 16);                           \
        cp16(smb + AT_K_H(buf) + d_,      sh_);                                   \
        cp16(smb + AT_K_H(buf) + d_ + 16, sh_ + 8);                               \
        if (withlo) {                                                             \
            const __half* sl_ = g_K1l + ((size_t)bh*1024 + (size_t)(kt)*64 + frow)*32 + fs2*8; \
            cp16(smb + AT_K_L(buf) + d_,      sl_);                               \
            cp16(smb + AT_K_L(buf) + d_ + 16, sl_ + 8);                           \
        }                                                                         \
    }
#define VFILL(buf, kt)                                                            \
    {                                                                             \
        const __half* sh_ = g_Vh + ((size_t)bh*1024 + (size_t)(kt)*64 + frow)*64 + fs4*8; \
        uint32_t d_ = (uint32_t)(frow * 144 + fs4 * 16);                          \
        _Pragma("unroll")                                                         \
        for (int u_ = 0; u_ < 4; ++u_)                                            \
            cp16(smb + AT_V_H(buf) + d_ + u_*16, sh_ + u_*8);                     \
    }

    KFILL(0, 0, false); CP_COMMIT();

    // stage Q slab (64 x 32 fp16 hi/lo)
    {
        const __half* qh = g_Q1h + ((size_t)bh*1024 + q0 + frow)*32 + fs2*8;
        const __half* ql = g_Q1l + ((size_t)bh*1024 + q0 + frow)*32 + fs2*8;
        uint32_t d = (uint32_t)(frow * 80 + fs2 * 16);
        *(uint4*)(sm + AT_Q_H + d)      = *(const uint4*)qh;
        *(uint4*)(sm + AT_Q_H + d + 16) = *(const uint4*)(qh + 8);
        *(uint4*)(sm + AT_Q_L + d)      = *(const uint4*)ql;
        *(uint4*)(sm + AT_Q_L + d + 16) = *(const uint4*)(ql + 8);
    }
    __syncthreads();

    uint32_t qfh[2][4], qfl[2][4];
    #pragma unroll
    for (int ks = 0; ks < 2; ++ks) {
        uint32_t off = (uint32_t)((wid * 16 + (lane & 15)) * 80
                                  + ks * 32 + ((lane >> 4) & 1) * 16);
        ldsm_x4(qfh[ks][0], qfh[ks][1], qfh[ks][2], qfh[ks][3], smb + AT_Q_H + off);
        ldsm_x4(qfl[ks][0], qfl[ks][1], qfl[ks][2], qfl[ks][3], smb + AT_Q_L + off);
    }

    const int gr0 = q0 + wid * 16 + (lane >> 2);

    // x4-merged K fragment address: one ldsm_x4 covers both k16 steps of tile nt
    const uint32_t kfoff = (uint32_t)(((lane & 7)) * 80 + (lane >> 3) * 16);

    #define SCOMP1(buf)                                                           \
    {                                                                             \
        const uint32_t khb = smb + AT_K_H(buf) + kfoff;                           \
        _Pragma("unroll")                                                         \
        for (int nt = 0; nt < 8; ++nt) {                                          \
            uint32_t kb[4];                                                       \
            ldsm_x4(kb[0], kb[1], kb[2], kb[3], khb + (uint32_t)(nt * 8 * 80));   \
            mma_f16(s[nt], qfh[0][0], qfh[0][1], qfh[0][2], qfh[0][3], kb[0], kb[1]); \
            mma_f16(s[nt], qfh[1][0], qfh[1][1], qfh[1][2], qfh[1][3], kb[2], kb[3]); \
        }                                                                         \
    }
    #define SCOMP3(buf)                                                           \
    {                                                                             \
        const uint32_t khb = smb + AT_K_H(buf) + kfoff;                           \
        const uint32_t klb = smb + AT_K_L(buf) + kfoff;                           \
        _Pragma("unroll")                                                         \
        for (int nt = 0; nt < 8; ++nt) {                                          \
            uint32_t kb[4], kl[4];                                                \
            ldsm_x4(kb[0], kb[1], kb[2], kb[3], khb + (uint32_t)(nt * 8 * 80));   \
            ldsm_x4(kl[0], kl[1], kl[2], kl[3], klb + (uint32_t)(nt * 8 * 80));   \
            mma_f16(s[nt], qfh[0][0], qfh[0][1], qfh[0][2], qfh[0][3], kb[0], kb[1]); \
            mma_f16(s[nt], qfh[1][0], qfh[1][1], qfh[1][2], qfh[1][3], kb[2], kb[3]); \
            mma_f16(s[nt], qfh[0][0], qfh[0][1], qfh[0][2], qfh[0][3], kl[0], kl[1]); \
            mma_f16(s[nt], qfh[1][0], qfh[1][1], qfh[1][2], qfh[1][3], kl[2], kl[3]); \
            mma_f16(s[nt], qfl[0][0], qfl[0][1], qfl[0][2], qfl[0][3], kb[0], kb[1]); \
            mma_f16(s[nt], qfl[1][0], qfl[1][1], qfl[1][2], qfl[1][3], kb[2], kb[3]); \
        }                                                                         \
    }
    #define SMASK(kt)                                                             \
    if ((kt) == nkt - 1) {                                                        \
        int cb = (kt) * 64 + (lane & 3) * 2;                                      \
        _Pragma("unroll")                                                         \
        for (int nt = 0; nt < 8; ++nt) {                                          \
            int c0 = cb + nt * 8;                                                 \
            if (c0     > gr0)     s[nt][0] = -1e30f;                              \
            if (c0 + 1 > gr0)     s[nt][1] = -1e30f;                              \
            if (c0     > gr0 + 8) s[nt][2] = -1e30f;                              \
            if (c0 + 1 > gr0 + 8) s[nt][3] = -1e30f;                              \
        }                                                                         \
    }

    // ================= Pass 1: l = sum exp2(s), 1-term QK =================
    float l0 = 0.f, l1 = 0.f;

    for (int kt = 0; kt < nkt; ++kt) {
        CP_WAIT(0);
        __syncthreads();
        if (kt + 1 < nkt) { KFILL((kt + 1) & 1, kt + 1, false); CP_COMMIT(); }

        float s[8][4] = {};
        SCOMP1(kt & 1);
        SMASK(kt);

        float a0 = 0.f, a1 = 0.f;
        #pragma unroll
        for (int nt = 0; nt < 8; ++nt) {
            a0 += ex2f(s[nt][0]) + ex2f(s[nt][1]);
            a1 += ex2f(s[nt][2]) + ex2f(s[nt][3]);
        }
        a0 += __shfl_xor_sync(0xffffffffu, a0, 1);
        a0 += __shfl_xor_sync(0xffffffffu, a0, 2);
        a1 += __shfl_xor_sync(0xffffffffu, a1, 1);
        a1 += __shfl_xor_sync(0xffffffffu, a1, 2);
        l0 += a0;
        l1 += a1;
    }
    const float li0 = 1.0f / l0, li1 = 1.0f / l1;

    // ================= Pass 2: P write + O = P @ V =================
    __syncthreads();
    KFILL(0, 0, true); VFILL(0, 0); CP_COMMIT();

    float o[8][4] = {};

    for (int kt = 0; kt < nkt; ++kt) {
        CP_WAIT(0);
        __syncthreads();
        if (kt + 1 < nkt) {
            KFILL((kt + 1) & 1, kt + 1, true);
            VFILL((kt + 1) & 1, kt + 1);
            CP_COMMIT();
        }

        float s[8][4] = {};
        SCOMP3(kt & 1);
        SMASK(kt);

        #pragma unroll
        for (int nt = 0; nt < 8; ++nt) {
            s[nt][0] = ex2f(s[nt][0]) * li0;
            s[nt][1] = ex2f(s[nt][1]) * li0;
            s[nt][2] = ex2f(s[nt][2]) * li1;
            s[nt][3] = ex2f(s[nt][3]) * li1;
        }

        {
            float* pr0 = Pout + ((size_t)bh * 1024 + gr0) * 1024 + kt * 64 + (lane & 3) * 2;
            float* pr1 = pr0 + 8 * 1024;
            #pragma unroll
            for (int nt = 0; nt < 8; ++nt) {
                *(float2*)&pr0[nt * 8] = make_float2(s[nt][0], s[nt][1]);
                *(float2*)&pr1[nt * 8] = make_float2(s[nt][2], s[nt][3]);
            }
        }

        // PV 1-term, x4t covers two n8 tiles
        const uint32_t vhb = smb + AT_V_H(kt & 1);
        #pragma unroll
        for (int ksv = 0; ksv < 4; ++ksv) {
            uint32_t ah[4];
            ah[0] = pack_h2(s[2*ksv][0],   s[2*ksv][1]);
            ah[1] = pack_h2(s[2*ksv][2],   s[2*ksv][3]);
            ah[2] = pack_h2(s[2*ksv+1][0], s[2*ksv+1][1]);
            ah[3] = pack_h2(s[2*ksv+1][2], s[2*ksv+1][3]);
            uint32_t vrow = (uint32_t)((ksv * 16 + (lane & 7) + ((lane >> 3) & 1) * 8) * 144
                                       + (lane >> 4) * 16);
            #pragma unroll
            for (int ntv = 0; ntv < 8; ntv += 2) {
                uint32_t v0, v1, v2, v3;
                ldsm_x4t(v0, v1, v2, v3, vhb + vrow + ntv * 16);
                mma_f16(o[ntv],     ah[0], ah[1], ah[2], ah[3], v0, v1);
                mma_f16(o[ntv + 1], ah[0], ah[1], ah[2], ah[3], v2, v3);
            }
        }
    }

    // zero-fill P tail (cols >= ncol)
    {
        float4 z = make_float4(0.f, 0.f, 0.f, 0.f);
        float* base0 = Pout + ((size_t)bh * 1024 + gr0) * 1024;
        float* base1 = base0 + 8 * 1024;
        for (int col = ncol + (lane & 3) * 4; col < 1024; col += 16) {
            *(float4*)&base0[col] = z;
            *(float4*)&base1[col] = z;
        }
    }

    // O epilogue -> qkvh (fp16); p already includes 1/l
    {
        const int b = bh >> 4, h = bh & 15;
        size_t i0 = ((size_t)(b * 1024 + gr0)) * 1024 + h * 64 + (lane & 3) * 2;
        size_t i1 = i0 + 8 * 1024;
        #pragma unroll
        for (int ntv = 0; ntv < 8; ++ntv) {
            *(uint32_t*)&qkvh[i0 + ntv * 8] = pack_h2(o[ntv][0], o[ntv][1]);
            *(uint32_t*)&qkvh[i1 + ntv * 8] = pack_h2(o[ntv][2], o[ntv][3]);
        }
    }
    #undef KFILL
    #undef VFILL
    #undef SCOMP1
    #undef SCOMP3
    #undef SMASK
}

// ---------------------------------------------------------------------------
// LayerNorm (unchanged)
// ---------------------------------------------------------------------------
__global__ void __launch_bounds__(256)
ln_kernel(const float* __restrict__ gamma,
          const float* __restrict__ beta,
          float* __restrict__ out)
{
    const int row = blockIdx.x;
    const int tid = threadIdx.x;
    const int c4  = tid * 4;
    const int hf  = tid >> 7;
    const int wrp = tid >> 5;

    float4 v = *(const float4*)&g_tmp[(size_t)row * 1024 + c4];
    float s  = v.x + v.y + v.z + v.w;
    float sq = v.x*v.x + v.y*v.y + v.z*v.z + v.w*v.w;
    #pragma unroll
    for (int off = 16; off > 0; off >>= 1) {
        s  += __shfl_xor_sync(0xffffffffu, s,  off);
        sq += __shfl_xor_sync(0xffffffffu, sq, off);
    }
    __shared__ float ss[8], sqq[8];
    if ((tid & 31) == 0) { ss[wrp] = s; sqq[wrp] = sq; }
    __syncthreads();
    float tot = 0.f, totq = 0.f;
    #pragma unroll
    for (int w = 0; w < 4; ++w) { tot += ss[hf * 4 + w]; totq += sqq[hf * 4 + w]; }

    float mu  = tot * (1.0f / 512.0f);
    float var = totq * (1.0f / 512.0f) - mu * mu;
    float rstd = rsqrtf(var + 1e-5f);

    int gc = c4 & 511;
    float4 g = *(const float4*)&gamma[gc];
    float4 b = *(const float4*)&beta[gc];
    float4 r;
    r.x = (v.x - mu) * rstd * g.x + b.x;
    r.y = (v.y - mu) * rstd * g.y + b.y;
    r.z = (v.z - mu) * rstd * g.z + b.z;
    r.w = (v.w - mu) * rstd * g.w + b.w;
    *(float4*)&out[(size_t)row * 1024 + c4] = r;
}

// ---------------------------------------------------------------------------
extern "C" void kernel_launch(void* const* d_in, const int* in_sizes, int n_in,
                              void* d_out, int out_size)
{
    const float* inQ  = (const float*)d_in[0];
    const float* inK  = (const float*)d_in[1];
    const float* inV  = (const float*)d_in[2];
    const float* WQ1  = (const float*)d_in[4];
    const float* WK1  = (const float*)d_in[5];
    const float* WV1  = (const float*)d_in[6];
    const float* WV2  = (const float*)d_in[9];
    const float* Wfc1 = (const float*)d_in[10];
    const float* Wfc2 = (const float*)d_in[11];
    const float* ln_g = (const float*)d_in[12];
    const float* ln_b = (const float*)d_in[13];

    float* out  = (float*)d_out;
    float* Pout = out + (size_t)B_ * S_ * D_;

    cudaFuncSetAttribute(attn_flash, cudaFuncAttributeMaxDynamicSharedMemorySize,
                         ATTN_SMEM);
    cudaFuncSetAttribute(mma_gemm<2>, cudaFuncAttributeMaxDynamicSharedMemorySize,
                         GEMM_SMEM);
    cudaFuncSetAttribute(mma_gemm<1>, cudaFuncAttributeMaxDynamicSharedMemorySize,
                         GEMM_SMEM);

    // 0) split GEMM operands to fp16 (Q,K hi+lo; V,W hi)
    presplit<<<dim3(256, 9), 256>>>(inQ, inK, inV, WQ1, WK1, WV1, WV2, Wfc1, Wfc2);
    // 1) projections: Q1,K1 (2-term), V1,V2 (1-term)
    mma_gemm<2><<<dim3(32, 4, 2), 512, GEMM_SMEM>>>(inQ, 0);
    mma_gemm<1><<<dim3(32, 4, 2), 512, GEMM_SMEM>>>(inQ, 2);
    // 2) flash attention (1 slab/CTA, LPT), x4 ldsm + ex2
    attn_flash<<<dim3(64, 16), 128, ATTN_SMEM>>>(Pout);
    // 3) FC + residual (1-term)
    mma_gemm<1><<<dim3(32, 4, 2), 512, GEMM_SMEM>>>(inQ, 4);
    // 4) LayerNorm -> final output
    ln_kernel<<<dim3(B_ * S_), 256>>>(ln_g, ln_b, out);
}

// round 13
// speedup vs baseline: 1.2549x; 1.1936x over previous
#include <cuda_runtime.h>
#include <cuda_fp16.h>
#include <math.h>
#include <stdint.h>

// Problem constants
#define B_  4
#define S_  1024
#define D_  1024
#define H_  16
#define DKH_ 32
#define DV_  64

// ---------------------------------------------------------------------------
// Scratch (device globals; no allocations allowed) — all fp16 hi-only now
// ---------------------------------------------------------------------------
__device__ __half pQh[4096*512];
__device__ __half pKh[4096*512];
__device__ __half pVh_[4096*1024];
__device__ __half pWh[6*512*512];
__device__ __half g_Q1h[64*1024*32];   // pre-scaled by log2e/sqrt(32)
__device__ __half g_K1h[64*1024*32];
__device__ __half g_Vh [64*1024*64];
__device__ __half qkvh[4096*1024];
__device__ float g_tmp[B_*S_*D_];

// ===========================================================================
// helpers
// ===========================================================================
__device__ __forceinline__ uint32_t smem_u32(const void* p) {
    uint32_t a;
    asm("{ .reg .u64 t; cvta.to.shared.u64 t, %1; cvt.u32.u64 %0, t; }"
        : "=r"(a) : "l"(p));
    return a;
}
__device__ __forceinline__ void ldsm_x4(uint32_t& r0, uint32_t& r1,
                                        uint32_t& r2, uint32_t& r3, uint32_t addr) {
    asm volatile("ldmatrix.sync.aligned.m8n8.x4.shared.b16 {%0,%1,%2,%3}, [%4];"
                 : "=r"(r0), "=r"(r1), "=r"(r2), "=r"(r3) : "r"(addr));
}
__device__ __forceinline__ void ldsm_x4t(uint32_t& r0, uint32_t& r1,
                                         uint32_t& r2, uint32_t& r3, uint32_t addr) {
    asm volatile("ldmatrix.sync.aligned.m8n8.x4.trans.shared.b16 {%0,%1,%2,%3}, [%4];"
                 : "=r"(r0), "=r"(r1), "=r"(r2), "=r"(r3) : "r"(addr));
}
__device__ __forceinline__ void ldsm_x2t(uint32_t& r0, uint32_t& r1, uint32_t addr) {
    asm volatile("ldmatrix.sync.aligned.m8n8.x2.trans.shared.b16 {%0,%1}, [%2];"
                 : "=r"(r0), "=r"(r1) : "r"(addr));
}
__device__ __forceinline__ void mma_f16(float* c, uint32_t a0, uint32_t a1,
                                        uint32_t a2, uint32_t a3,
                                        uint32_t b0, uint32_t b1) {
    asm volatile("mma.sync.aligned.m16n8k16.row.col.f32.f16.f16.f32 "
                 "{%0,%1,%2,%3}, {%4,%5,%6,%7}, {%8,%9}, {%0,%1,%2,%3};"
                 : "+f"(c[0]), "+f"(c[1]), "+f"(c[2]), "+f"(c[3])
                 : "r"(a0), "r"(a1), "r"(a2), "r"(a3), "r"(b0), "r"(b1));
}
__device__ __forceinline__ float ex2f(float x) {
    float r;
    asm("ex2.approx.f32 %0, %1;" : "=f"(r) : "f"(x));
    return r;
}
__device__ __forceinline__ uint32_t pack_h2(float x, float y) {
    __half2 t = __floats2half2_rn(x, y);
    return *reinterpret_cast<uint32_t*>(&t);
}
__device__ __forceinline__ void cp16(uint32_t dst, const void* src) {
    asm volatile("cp.async.cg.shared.global [%0], [%1], 16;"
                 :: "r"(dst), "l"(src));
}
#define CP_COMMIT()  asm volatile("cp.async.commit_group;" ::: "memory")
#define CP_WAIT(N)   asm volatile("cp.async.wait_group %0;" :: "n"(N) : "memory")

// ===========================================================================
// presplit: fp32 -> fp16 hi for all GEMM operands.
// segs: 0=Q[:, :512], 1=K[:, :512], 2=V (full), 3..8 = W0..W5
// ===========================================================================
__global__ void __launch_bounds__(256)
presplit(const float* __restrict__ inQ, const float* __restrict__ inK,
         const float* __restrict__ inV,
         const float* __restrict__ W0, const float* __restrict__ W1,
         const float* __restrict__ W2, const float* __restrict__ W3,
         const float* __restrict__ W4, const float* __restrict__ W5)
{
    const int seg = blockIdx.y;
    const int gid = blockIdx.x * 256 + threadIdx.x;
    const int stride4 = gridDim.x * 256 * 4;

    if (seg < 2) {
        const float* s = seg ? inK : inQ;
        __half* dh = seg ? pKh : pQh;
        for (int i = gid * 4; i < 4096 * 512; i += stride4) {
            int row = i >> 9, col = i & 511;
            float4 v = *(const float4*)&s[(size_t)row * 1024 + col];
            *(uint2*)&dh[i] = make_uint2(pack_h2(v.x, v.y), pack_h2(v.z, v.w));
        }
    } else if (seg == 2) {
        for (int i = gid * 4; i < 4096 * 1024; i += stride4) {
            float4 v = *(const float4*)&inV[i];
            *(uint2*)&pVh_[i] = make_uint2(pack_h2(v.x, v.y), pack_h2(v.z, v.w));
        }
    } else {
        const int w = seg - 3;
        const float* s = (w == 0) ? W0 : (w == 1) ? W1 : (w == 2) ? W2
                       : (w == 3) ? W3 : (w == 4) ? W4 : W5;
        __half* dh = pWh + (size_t)w * 262144;
        for (int i = gid * 4; i < 262144; i += stride4) {
            float4 v = *(const float4*)&s[i];
            *(uint2*)&dh[i] = make_uint2(pack_h2(v.x, v.y), pack_h2(v.z, v.w));
        }
    }
}

// ===========================================================================
// HMMA GEMM, 1-term fp16: 512 threads, 128x128 tile, K chunk 32, 3-stage.
// mode: 0=Q1(scaled), 1=K1, 2=V1, 3=V2, 4=FC half0 (+res), 5=FC half1 (+res)
// ===========================================================================
#define APITCH 80
#define BPITCH 272
#define ST_SZ  18944u
#define ST_AH(s) ((s) * ST_SZ)
#define ST_BH(s) ((s) * ST_SZ + 10240u)
#define GEMM_SMEM (3 * 18944)

__global__ void __launch_bounds__(512, 1)
mma_gemm(const float* __restrict__ inQ, int mode_base)
{
    extern __shared__ unsigned char sm[];
    const uint32_t smb = smem_u32(sm);

    const int mode = mode_base + blockIdx.z;
    const __half *pAh;
    int apitch, aoff;
    switch (mode) {
        case 0: pAh = pQh;  apitch = 512;  aoff = 0;   break;
        case 1: pAh = pKh;  apitch = 512;  aoff = 0;   break;
        case 2: pAh = pVh_; apitch = 1024; aoff = 0;   break;
        case 3: pAh = pVh_; apitch = 1024; aoff = 512; break;
        case 4: pAh = qkvh; apitch = 1024; aoff = 0;   break;
        default:pAh = qkvh; apitch = 1024; aoff = 512; break;
    }
    const __half* wh = pWh + (size_t)mode * 262144;

    const int m0 = blockIdx.x * 128;
    const int n0 = blockIdx.y * 128;
    const int tid  = threadIdx.x;
    const int wid  = tid >> 5;
    const int lane = tid & 31;
    const int wy = wid >> 2;
    const int wx = wid & 3;

    const int ar = tid >> 2, aseg = tid & 3;
    const int br = tid >> 4, bseg = tid & 15;

    #define GFILL(st, k0)                                                         \
    {                                                                             \
        const __half* sha = pAh + (size_t)(m0 + ar) * apitch + aoff + (k0) + aseg * 8; \
        cp16(smb + ST_AH(st) + (uint32_t)(ar * APITCH + aseg * 16), sha);         \
        const __half* shb = wh + (size_t)((k0) + br) * 512 + n0 + bseg * 8;       \
        cp16(smb + ST_BH(st) + (uint32_t)(br * BPITCH + bseg * 16), shb);         \
        CP_COMMIT();                                                              \
    }

    float c[2][4][4] = {};

    const int a_row_in_tile = lane & 15;
    const int a_kseg        = (lane >> 4) & 1;
    const int b_krow        = (lane & 7) + ((lane >> 3) & 1) * 8;

    GFILL(0, 0);
    GFILL(1, 32);

    for (int chunk = 0; chunk < 16; ++chunk) {
        if (chunk + 1 < 16) { CP_WAIT(1); } else { CP_WAIT(0); }
        __syncthreads();
        if (chunk + 2 < 16) {
            int st = (chunk + 2) % 3;
            GFILL(st, (chunk + 2) * 32);
        }
        const int cs = chunk % 3;
        const uint32_t ahb = smb + ST_AH(cs);
        const uint32_t bhb = smb + ST_BH(cs);

        #pragma unroll
        for (int ks = 0; ks < 2; ++ks) {
            uint32_t ahf[2][4];
            #pragma unroll
            for (int mt = 0; mt < 2; ++mt) {
                int row = wy * 32 + mt * 16 + a_row_in_tile;
                uint32_t aoffb = (uint32_t)(row * APITCH + ks * 32 + a_kseg * 16);
                ldsm_x4(ahf[mt][0], ahf[mt][1], ahf[mt][2], ahf[mt][3], ahb + aoffb);
            }
            uint32_t bhf[4][2];
            #pragma unroll
            for (int nt = 0; nt < 4; ++nt) {
                uint32_t boffb = (uint32_t)((ks * 16 + b_krow) * BPITCH
                                            + (wx * 32 + nt * 8) * 2);
                ldsm_x2t(bhf[nt][0], bhf[nt][1], bhb + boffb);
            }
            #pragma unroll
            for (int mt = 0; mt < 2; ++mt) {
                #pragma unroll
                for (int nt = 0; nt < 4; ++nt) {
                    mma_f16(c[mt][nt], ahf[mt][0], ahf[mt][1], ahf[mt][2], ahf[mt][3],
                            bhf[nt][0], bhf[nt][1]);
                }
            }
        }
    }

    // ---- epilogue ----
    const int gid = lane >> 2;
    const int tig = lane & 3;

    #pragma unroll
    for (int mt = 0; mt < 2; ++mt) {
        int row = m0 + wy * 32 + mt * 16 + gid;
        int b = row >> 10, s = row & 1023;
        #pragma unroll
        for (int nt = 0; nt < 4; ++nt) {
            int col = n0 + wx * 32 + nt * 8 + tig * 2;
            float2 v01 = make_float2(c[mt][nt][0], c[mt][nt][1]);
            float2 v23 = make_float2(c[mt][nt][2], c[mt][nt][3]);
            if (mode <= 1) {
                int h = col >> 5, d = col & 31;
                __half* dh = (mode == 0) ? g_Q1h : g_K1h;
                // Q scale: log2(e)/sqrt(32) so softmax uses ex2 directly
                float sc = (mode == 0) ? 0.25503487350122697f : 1.0f;
                size_t base = ((size_t)(b * 16 + h) * 1024) * 32 + d;
                *(uint32_t*)&dh[base + (size_t)s * 32]       = pack_h2(v01.x * sc, v01.y * sc);
                *(uint32_t*)&dh[base + (size_t)(s + 8) * 32] = pack_h2(v23.x * sc, v23.y * sc);
            } else if (mode <= 3) {
                int h = col >> 5, d = (col & 31) + (mode == 3 ? 32 : 0);
                size_t base = ((size_t)(b * 16 + h) * 1024) * 64 + d;
                *(uint32_t*)&g_Vh[base + (size_t)s * 64]       = pack_h2(v01.x, v01.y);
                *(uint32_t*)&g_Vh[base + (size_t)(s + 8) * 64] = pack_h2(v23.x, v23.y);
            } else {
                int half = mode - 4;
                size_t idx0 = (size_t)row * 1024 + half * 512 + col;
                size_t idx1 = idx0 + 8 * 1024;
                float2 r0 = *(const float2*)&inQ[idx0];
                float2 r1 = *(const float2*)&inQ[idx1];
                *(float2*)&g_tmp[idx0] = make_float2(v01.x + r0.x, v01.y + r0.y);
                *(float2*)&g_tmp[idx1] = make_float2(v23.x + r1.x, v23.y + r1.y);
            }
        }
    }
    #undef GFILL
}

// ===========================================================================
// Flash attention: 1 slab/CTA, 1024 CTAs, LPT. Pure fp16 1-term QK/PV,
// ex2 softmax, x4 ldsm. smem 28KB -> 5 CTAs/SM.
// ===========================================================================
#define AT_K_H(buf) ((buf) * 5120u)
#define AT_V_H(buf) (10240u + (buf) * 9216u)
#define AT_Q_H 10240u            /* overlay on V region (V unused in pass 1) */
#define ATTN_SMEM 28672

__global__ void __launch_bounds__(128, 5)
attn_flash(float* __restrict__ Pout)
{
    extern __shared__ unsigned char sm[];
    const uint32_t smb = smem_u32(sm);

    const int bh = blockIdx.x;
    const int qs = 15 - (int)blockIdx.y;   // LPT: heavy slabs first
    const int q0 = qs * 64;
    const int nkt = qs + 1;
    const int ncol = nkt * 64;
    const int tid = threadIdx.x, wid = tid >> 5, lane = tid & 31;

    const int frow = tid >> 1;
    const int fs2  = (tid & 1) * 2;
    const int fs4  = (tid & 1) * 4;

#define KFILL(buf, kt)                                                            \
    {                                                                             \
        const __half* sh_ = g_K1h + ((size_t)bh*1024 + (size_t)(kt)*64 + frow)*32 + fs2*8; \
        uint32_t d_ = (uint32_t)(frow * 80 + fs2 * 16);                           \
        cp16(smb + AT_K_H(buf) + d_,      sh_);                                   \
        cp16(smb + AT_K_H(buf) + d_ + 16, sh_ + 8);                               \
    }
#define VFILL(buf, kt)                                                            \
    {                                                                             \
        const __half* sh_ = g_Vh + ((size_t)bh*1024 + (size_t)(kt)*64 + frow)*64 + fs4*8; \
        uint32_t d_ = (uint32_t)(frow * 144 + fs4 * 16);                          \
        _Pragma("unroll")                                                         \
        for (int u_ = 0; u_ < 4; ++u_)                                            \
            cp16(smb + AT_V_H(buf) + d_ + u_*16, sh_ + u_*8);                     \
    }

    KFILL(0, 0); CP_COMMIT();

    // stage Q slab (64 x 32 fp16 hi)
    {
        const __half* qh = g_Q1h + ((size_t)bh*1024 + q0 + frow)*32 + fs2*8;
        uint32_t d = (uint32_t)(frow * 80 + fs2 * 16);
        *(uint4*)(sm + AT_Q_H + d)      = *(const uint4*)qh;
        *(uint4*)(sm + AT_Q_H + d + 16) = *(const uint4*)(qh + 8);
    }
    __syncthreads();

    uint32_t qfh[2][4];
    #pragma unroll
    for (int ks = 0; ks < 2; ++ks) {
        uint32_t off = (uint32_t)((wid * 16 + (lane & 15)) * 80
                                  + ks * 32 + ((lane >> 4) & 1) * 16);
        ldsm_x4(qfh[ks][0], qfh[ks][1], qfh[ks][2], qfh[ks][3], smb + AT_Q_H + off);
    }

    const int gr0 = q0 + wid * 16 + (lane >> 2);

    // x4-merged K fragment address: one ldsm_x4 covers both k16 steps of tile nt
    const uint32_t kfoff = (uint32_t)(((lane & 7)) * 80 + (lane >> 3) * 16);

    #define SCOMP(buf)                                                            \
    {                                                                             \
        const uint32_t khb = smb + AT_K_H(buf) + kfoff;                           \
        _Pragma("unroll")                                                         \
        for (int nt = 0; nt < 8; ++nt) {                                          \
            uint32_t kb[4];                                                       \
            ldsm_x4(kb[0], kb[1], kb[2], kb[3], khb + (uint32_t)(nt * 8 * 80));   \
            mma_f16(s[nt], qfh[0][0], qfh[0][1], qfh[0][2], qfh[0][3], kb[0], kb[1]); \
            mma_f16(s[nt], qfh[1][0], qfh[1][1], qfh[1][2], qfh[1][3], kb[2], kb[3]); \
        }                                                                         \
    }
    #define SMASK(kt)                                                             \
    if ((kt) == nkt - 1) {                                                        \
        int cb = (kt) * 64 + (lane & 3) * 2;                                      \
        _Pragma("unroll")                                                         \
        for (int nt = 0; nt < 8; ++nt) {                                          \
            int c0 = cb + nt * 8;                                                 \
            if (c0     > gr0)     s[nt][0] = -1e30f;                              \
            if (c0 + 1 > gr0)     s[nt][1] = -1e30f;                              \
            if (c0     > gr0 + 8) s[nt][2] = -1e30f;                              \
            if (c0 + 1 > gr0 + 8) s[nt][3] = -1e30f;                              \
        }                                                                         \
    }

    // ================= Pass 1: l = sum exp2(s) =================
    float l0 = 0.f, l1 = 0.f;

    for (int kt = 0; kt < nkt; ++kt) {
        CP_WAIT(0);
        __syncthreads();
        if (kt + 1 < nkt) { KFILL((kt + 1) & 1, kt + 1); CP_COMMIT(); }

        float s[8][4] = {};
        SCOMP(kt & 1);
        SMASK(kt);

        float a0 = 0.f, a1 = 0.f;
        #pragma unroll
        for (int nt = 0; nt < 8; ++nt) {
            a0 += ex2f(s[nt][0]) + ex2f(s[nt][1]);
            a1 += ex2f(s[nt][2]) + ex2f(s[nt][3]);
        }
        a0 += __shfl_xor_sync(0xffffffffu, a0, 1);
        a0 += __shfl_xor_sync(0xffffffffu, a0, 2);
        a1 += __shfl_xor_sync(0xffffffffu, a1, 1);
        a1 += __shfl_xor_sync(0xffffffffu, a1, 2);
        l0 += a0;
        l1 += a1;
    }
    const float li0 = 1.0f / l0, li1 = 1.0f / l1;

    // ================= Pass 2: P write + O = P @ V =================
    __syncthreads();
    KFILL(0, 0); VFILL(0, 0); CP_COMMIT();

    float o[8][4] = {};

    for (int kt = 0; kt < nkt; ++kt) {
        CP_WAIT(0);
        __syncthreads();
        if (kt + 1 < nkt) {
            KFILL((kt + 1) & 1, kt + 1);
            VFILL((kt + 1) & 1, kt + 1);
            CP_COMMIT();
        }

        float s[8][4] = {};
        SCOMP(kt & 1);
        SMASK(kt);

        #pragma unroll
        for (int nt = 0; nt < 8; ++nt) {
            s[nt][0] = ex2f(s[nt][0]) * li0;
            s[nt][1] = ex2f(s[nt][1]) * li0;
            s[nt][2] = ex2f(s[nt][2]) * li1;
            s[nt][3] = ex2f(s[nt][3]) * li1;
        }

        {
            float* pr0 = Pout + ((size_t)bh * 1024 + gr0) * 1024 + kt * 64 + (lane & 3) * 2;
            float* pr1 = pr0 + 8 * 1024;
            #pragma unroll
            for (int nt = 0; nt < 8; ++nt) {
                *(float2*)&pr0[nt * 8] = make_float2(s[nt][0], s[nt][1]);
                *(float2*)&pr1[nt * 8] = make_float2(s[nt][2], s[nt][3]);
            }
        }

        // PV 1-term, x4t covers two n8 tiles
        const uint32_t vhb = smb + AT_V_H(kt & 1);
        #pragma unroll
        for (int ksv = 0; ksv < 4; ++ksv) {
            uint32_t ah[4];
            ah[0] = pack_h2(s[2*ksv][0],   s[2*ksv][1]);
            ah[1] = pack_h2(s[2*ksv][2],   s[2*ksv][3]);
            ah[2] = pack_h2(s[2*ksv+1][0], s[2*ksv+1][1]);
            ah[3] = pack_h2(s[2*ksv+1][2], s[2*ksv+1][3]);
            uint32_t vrow = (uint32_t)((ksv * 16 + (lane & 7) + ((lane >> 3) & 1) * 8) * 144
                                       + (lane >> 4) * 16);
            #pragma unroll
            for (int ntv = 0; ntv < 8; ntv += 2) {
                uint32_t v0, v1, v2, v3;
                ldsm_x4t(v0, v1, v2, v3, vhb + vrow + ntv * 16);
                mma_f16(o[ntv],     ah[0], ah[1], ah[2], ah[3], v0, v1);
                mma_f16(o[ntv + 1], ah[0], ah[1], ah[2], ah[3], v2, v3);
            }
        }
    }

    // zero-fill P tail (cols >= ncol)
    {
        float4 z = make_float4(0.f, 0.f, 0.f, 0.f);
        float* base0 = Pout + ((size_t)bh * 1024 + gr0) * 1024;
        float* base1 = base0 + 8 * 1024;
        for (int col = ncol + (lane & 3) * 4; col < 1024; col += 16) {
            *(float4*)&base0[col] = z;
            *(float4*)&base1[col] = z;
        }
    }

    // O epilogue -> qkvh (fp16); p already includes 1/l
    {
        const int b = bh >> 4, h = bh & 15;
        size_t i0 = ((size_t)(b * 1024 + gr0)) * 1024 + h * 64 + (lane & 3) * 2;
        size_t i1 = i0 + 8 * 1024;
        #pragma unroll
        for (int ntv = 0; ntv < 8; ++ntv) {
            *(uint32_t*)&qkvh[i0 + ntv * 8] = pack_h2(o[ntv][0], o[ntv][1]);
            *(uint32_t*)&qkvh[i1 + ntv * 8] = pack_h2(o[ntv][2], o[ntv][3]);
        }
    }
    #undef KFILL
    #undef VFILL
    #undef SCOMP
    #undef SMASK
}

// ---------------------------------------------------------------------------
// LayerNorm (unchanged)
// ---------------------------------------------------------------------------
__global__ void __launch_bounds__(256)
ln_kernel(const float* __restrict__ gamma,
          const float* __restrict__ beta,
          float* __restrict__ out)
{
    const int row = blockIdx.x;
    const int tid = threadIdx.x;
    const int c4  = tid * 4;
    const int hf  = tid >> 7;
    const int wrp = tid >> 5;

    float4 v = *(const float4*)&g_tmp[(size_t)row * 1024 + c4];
    float s  = v.x + v.y + v.z + v.w;
    float sq = v.x*v.x + v.y*v.y + v.z*v.z + v.w*v.w;
    #pragma unroll
    for (int off = 16; off > 0; off >>= 1) {
        s  += __shfl_xor_sync(0xffffffffu, s,  off);
        sq += __shfl_xor_sync(0xffffffffu, sq, off);
    }
    __shared__ float ss[8], sqq[8];
    if ((tid & 31) == 0) { ss[wrp] = s; sqq[wrp] = sq; }
    __syncthreads();
    float tot = 0.f, totq = 0.f;
    #pragma unroll
    for (int w = 0; w < 4; ++w) { tot += ss[hf * 4 + w]; totq += sqq[hf * 4 + w]; }

    float mu  = tot * (1.0f / 512.0f);
    float var = totq * (1.0f / 512.0f) - mu * mu;
    float rstd = rsqrtf(var + 1e-5f);

    int gc = c4 & 511;
    float4 g = *(const float4*)&gamma[gc];
    float4 b = *(const float4*)&beta[gc];
    float4 r;
    r.x = (v.x - mu) * rstd * g.x + b.x;
    r.y = (v.y - mu) * rstd * g.y + b.y;
    r.z = (v.z - mu) * rstd * g.z + b.z;
    r.w = (v.w - mu) * rstd * g.w + b.w;
    *(float4*)&out[(size_t)row * 1024 + c4] = r;
}

// ---------------------------------------------------------------------------
extern "C" void kernel_launch(void* const* d_in, const int* in_sizes, int n_in,
                              void* d_out, int out_size)
{
    const float* inQ  = (const float*)d_in[0];
    const float* inK  = (const float*)d_in[1];
    const float* inV  = (const float*)d_in[2];
    const float* WQ1  = (const float*)d_in[4];
    const float* WK1  = (const float*)d_in[5];
    const float* WV1  = (const float*)d_in[6];
    const float* WV2  = (const float*)d_in[9];
    const float* Wfc1 = (const float*)d_in[10];
    const float* Wfc2 = (const float*)d_in[11];
    const float* ln_g = (const float*)d_in[12];
    const float* ln_b = (const float*)d_in[13];

    float* out  = (float*)d_out;
    float* Pout = out + (size_t)B_ * S_ * D_;

    cudaFuncSetAttribute(attn_flash, cudaFuncAttributeMaxDynamicSharedMemorySize,
                         ATTN_SMEM);
    cudaFuncSetAttribute(mma_gemm, cudaFuncAttributeMaxDynamicSharedMemorySize,
                         GEMM_SMEM);

    // 0) convert GEMM operands to fp16
    presplit<<<dim3(256, 9), 256>>>(inQ, inK, inV, WQ1, WK1, WV1, WV2, Wfc1, Wfc2);
    // 1) projections: Q1, K1, V1, V2 (single launch, 1-term)
    mma_gemm<<<dim3(32, 4, 4), 512, GEMM_SMEM>>>(inQ, 0);
    // 2) flash attention (1 slab/CTA, LPT), pure fp16, 5 CTAs/SM
    attn_flash<<<dim3(64, 16), 128, ATTN_SMEM>>>(Pout);
    // 3) FC + residual (1-term)
    mma_gemm<<<dim3(32, 4, 2), 512, GEMM_SMEM>>>(inQ, 4);
    // 4) LayerNorm -> final output
    ln_kernel<<<dim3(B_ * S_), 256>>>(ln_g, ln_b, out);
}

// round 14
// speedup vs baseline: 1.3025x; 1.0380x over previous
#include <cuda_runtime.h>
#include <cuda_fp16.h>
#include <math.h>
#include <stdint.h>

// Problem constants
#define B_  4
#define S_  1024
#define D_  1024
#define H_  16
#define DKH_ 32
#define DV_  64

// ---------------------------------------------------------------------------
// Scratch (device globals; no allocations allowed) — all fp16 hi-only
// ---------------------------------------------------------------------------
__device__ __half pQh[4096*512];
__device__ __half pKh[4096*512];
__device__ __half pVh_[4096*1024];
__device__ __half pWh[6*512*512];
__device__ __half g_Q1h[64*1024*32];   // pre-scaled by log2e/sqrt(32)
__device__ __half g_K1h[64*1024*32];
__device__ __half g_Vh [64*1024*64];
__device__ __half qkvh[4096*1024];
__device__ float g_tmp[B_*S_*D_];

// ===========================================================================
// helpers
// ===========================================================================
__device__ __forceinline__ uint32_t smem_u32(const void* p) {
    uint32_t a;
    asm("{ .reg .u64 t; cvta.to.shared.u64 t, %1; cvt.u32.u64 %0, t; }"
        : "=r"(a) : "l"(p));
    return a;
}
__device__ __forceinline__ void ldsm_x4(uint32_t& r0, uint32_t& r1,
                                        uint32_t& r2, uint32_t& r3, uint32_t addr) {
    asm volatile("ldmatrix.sync.aligned.m8n8.x4.shared.b16 {%0,%1,%2,%3}, [%4];"
                 : "=r"(r0), "=r"(r1), "=r"(r2), "=r"(r3) : "r"(addr));
}
__device__ __forceinline__ void ldsm_x4t(uint32_t& r0, uint32_t& r1,
                                         uint32_t& r2, uint32_t& r3, uint32_t addr) {
    asm volatile("ldmatrix.sync.aligned.m8n8.x4.trans.shared.b16 {%0,%1,%2,%3}, [%4];"
                 : "=r"(r0), "=r"(r1), "=r"(r2), "=r"(r3) : "r"(addr));
}
__device__ __forceinline__ void ldsm_x2t(uint32_t& r0, uint32_t& r1, uint32_t addr) {
    asm volatile("ldmatrix.sync.aligned.m8n8.x2.trans.shared.b16 {%0,%1}, [%2];"
                 : "=r"(r0), "=r"(r1) : "r"(addr));
}
__device__ __forceinline__ void mma_f16(float* c, uint32_t a0, uint32_t a1,
                                        uint32_t a2, uint32_t a3,
                                        uint32_t b0, uint32_t b1) {
    asm volatile("mma.sync.aligned.m16n8k16.row.col.f32.f16.f16.f32 "
                 "{%0,%1,%2,%3}, {%4,%5,%6,%7}, {%8,%9}, {%0,%1,%2,%3};"
                 : "+f"(c[0]), "+f"(c[1]), "+f"(c[2]), "+f"(c[3])
                 : "r"(a0), "r"(a1), "r"(a2), "r"(a3), "r"(b0), "r"(b1));
}
__device__ __forceinline__ float ex2f(float x) {
    float r;
    asm("ex2.approx.f32 %0, %1;" : "=f"(r) : "f"(x));
    return r;
}
__device__ __forceinline__ uint32_t pack_h2(float x, float y) {
    __half2 t = __floats2half2_rn(x, y);
    return *reinterpret_cast<uint32_t*>(&t);
}
__device__ __forceinline__ void cp16(uint32_t dst, const void* src) {
    asm volatile("cp.async.cg.shared.global [%0], [%1], 16;"
                 :: "r"(dst), "l"(src));
}
#define CP_COMMIT()  asm volatile("cp.async.commit_group;" ::: "memory")
#define CP_WAIT(N)   asm volatile("cp.async.wait_group %0;" :: "n"(N) : "memory")

// ===========================================================================
// presplit: fp32 -> fp16 hi for all GEMM operands. (unchanged)
// ===========================================================================
__global__ void __launch_bounds__(256)
presplit(const float* __restrict__ inQ, const float* __restrict__ inK,
         const float* __restrict__ inV,
         const float* __restrict__ W0, const float* __restrict__ W1,
         const float* __restrict__ W2, const float* __restrict__ W3,
         const float* __restrict__ W4, const float* __restrict__ W5)
{
    const int seg = blockIdx.y;
    const int gid = blockIdx.x * 256 + threadIdx.x;
    const int stride4 = gridDim.x * 256 * 4;

    if (seg < 2) {
        const float* s = seg ? inK : inQ;
        __half* dh = seg ? pKh : pQh;
        for (int i = gid * 4; i < 4096 * 512; i += stride4) {
            int row = i >> 9, col = i & 511;
            float4 v = *(const float4*)&s[(size_t)row * 1024 + col];
            *(uint2*)&dh[i] = make_uint2(pack_h2(v.x, v.y), pack_h2(v.z, v.w));
        }
    } else if (seg == 2) {
        for (int i = gid * 4; i < 4096 * 1024; i += stride4) {
            float4 v = *(const float4*)&inV[i];
            *(uint2*)&pVh_[i] = make_uint2(pack_h2(v.x, v.y), pack_h2(v.z, v.w));
        }
    } else {
        const int w = seg - 3;
        const float* s = (w == 0) ? W0 : (w == 1) ? W1 : (w == 2) ? W2
                       : (w == 3) ? W3 : (w == 4) ? W4 : W5;
        __half* dh = pWh + (size_t)w * 262144;
        for (int i = gid * 4; i < 262144; i += stride4) {
            float4 v = *(const float4*)&s[i];
            *(uint2*)&dh[i] = make_uint2(pack_h2(v.x, v.y), pack_h2(v.z, v.w));
        }
    }
}

// ===========================================================================
// HMMA GEMM, 1-term fp16: 512 threads / 16 warps, CTA tile 256x128,
// warp tile 64x32, K chunk 32, 3-stage cp.async pipeline.
// mode: 0=Q1(scaled), 1=K1, 2=V1, 3=V2, 4=FC half0 (+res), 5=FC half1 (+res)
// ===========================================================================
#define APITCH 80
#define BPITCH 272
#define ST_SZ  29184u
#define ST_AH(s) ((s) * ST_SZ)
#define ST_BH(s) ((s) * ST_SZ + 20480u)
#define GEMM_SMEM (3 * 29184)

__global__ void __launch_bounds__(512, 1)
mma_gemm(const float* __restrict__ inQ, int mode_base)
{
    extern __shared__ unsigned char sm[];
    const uint32_t smb = smem_u32(sm);

    const int mode = mode_base + blockIdx.z;
    const __half *pAh;
    int apitch, aoff;
    switch (mode) {
        case 0: pAh = pQh;  apitch = 512;  aoff = 0;   break;
        case 1: pAh = pKh;  apitch = 512;  aoff = 0;   break;
        case 2: pAh = pVh_; apitch = 1024; aoff = 0;   break;
        case 3: pAh = pVh_; apitch = 1024; aoff = 512; break;
        case 4: pAh = qkvh; apitch = 1024; aoff = 0;   break;
        default:pAh = qkvh; apitch = 1024; aoff = 512; break;
    }
    const __half* wh = pWh + (size_t)mode * 262144;

    const int m0 = blockIdx.x * 256;
    const int n0 = blockIdx.y * 128;
    const int tid  = threadIdx.x;
    const int wid  = tid >> 5;
    const int lane = tid & 31;
    const int wy = wid >> 2;        // 0..3 (64 rows each)
    const int wx = wid & 3;         // 0..3 (32 cols each)

    // fills: A 256 rows x 4 segs = 1024 cp16 (2/thread); B 32x16 = 512 (1/thread)
    const int ar = tid >> 1, aseg2 = (tid & 1) * 2;
    const int br = tid >> 4, bseg = tid & 15;

    #define GFILL(st, k0)                                                         \
    {                                                                             \
        const __half* sha = pAh + (size_t)(m0 + ar) * apitch + aoff + (k0) + aseg2 * 8; \
        uint32_t da = (uint32_t)(ar * APITCH + aseg2 * 16);                       \
        cp16(smb + ST_AH(st) + da,      sha);                                     \
        cp16(smb + ST_AH(st) + da + 16, sha + 8);                                 \
        const __half* shb = wh + (size_t)((k0) + br) * 512 + n0 + bseg * 8;       \
        cp16(smb + ST_BH(st) + (uint32_t)(br * BPITCH + bseg * 16), shb);         \
        CP_COMMIT();                                                              \
    }

    float c[4][4][4] = {};

    const int a_row_in_tile = lane & 15;
    const int a_kseg        = (lane >> 4) & 1;
    const int b_krow        = (lane & 7) + ((lane >> 3) & 1) * 8;

    GFILL(0, 0);
    GFILL(1, 32);

    for (int chunk = 0; chunk < 16; ++chunk) {
        if (chunk + 1 < 16) { CP_WAIT(1); } else { CP_WAIT(0); }
        __syncthreads();
        if (chunk + 2 < 16) {
            int st = (chunk + 2) % 3;
            GFILL(st, (chunk + 2) * 32);
        }
        const int cs = chunk % 3;
        const uint32_t ahb = smb + ST_AH(cs);
        const uint32_t bhb = smb + ST_BH(cs);

        #pragma unroll
        for (int ks = 0; ks < 2; ++ks) {
            uint32_t ahf[4][4];
            #pragma unroll
            for (int mt = 0; mt < 4; ++mt) {
                int row = wy * 64 + mt * 16 + a_row_in_tile;
                uint32_t aoffb = (uint32_t)(row * APITCH + ks * 32 + a_kseg * 16);
                ldsm_x4(ahf[mt][0], ahf[mt][1], ahf[mt][2], ahf[mt][3], ahb + aoffb);
            }
            uint32_t bhf[4][2];
            #pragma unroll
            for (int nt = 0; nt < 4; ++nt) {
                uint32_t boffb = (uint32_t)((ks * 16 + b_krow) * BPITCH
                                            + (wx * 32 + nt * 8) * 2);
                ldsm_x2t(bhf[nt][0], bhf[nt][1], bhb + boffb);
            }
            #pragma unroll
            for (int mt = 0; mt < 4; ++mt) {
                #pragma unroll
                for (int nt = 0; nt < 4; ++nt) {
                    mma_f16(c[mt][nt], ahf[mt][0], ahf[mt][1], ahf[mt][2], ahf[mt][3],
                            bhf[nt][0], bhf[nt][1]);
                }
            }
        }
    }

    // ---- epilogue ----
    const int gid = lane >> 2;
    const int tig = lane & 3;

    #pragma unroll
    for (int mt = 0; mt < 4; ++mt) {
        int row = m0 + wy * 64 + mt * 16 + gid;
        int b = row >> 10, s = row & 1023;
        #pragma unroll
        for (int nt = 0; nt < 4; ++nt) {
            int col = n0 + wx * 32 + nt * 8 + tig * 2;
            float2 v01 = make_float2(c[mt][nt][0], c[mt][nt][1]);
            float2 v23 = make_float2(c[mt][nt][2], c[mt][nt][3]);
            if (mode <= 1) {
                int h = col >> 5, d = col & 31;
                __half* dh = (mode == 0) ? g_Q1h : g_K1h;
                // Q scale: log2(e)/sqrt(32) so softmax uses ex2 directly
                float sc = (mode == 0) ? 0.25503487350122697f : 1.0f;
                size_t base = ((size_t)(b * 16 + h) * 1024) * 32 + d;
                *(uint32_t*)&dh[base + (size_t)s * 32]       = pack_h2(v01.x * sc, v01.y * sc);
                *(uint32_t*)&dh[base + (size_t)(s + 8) * 32] = pack_h2(v23.x * sc, v23.y * sc);
            } else if (mode <= 3) {
                int h = col >> 5, d = (col & 31) + (mode == 3 ? 32 : 0);
                size_t base = ((size_t)(b * 16 + h) * 1024) * 64 + d;
                *(uint32_t*)&g_Vh[base + (size_t)s * 64]       = pack_h2(v01.x, v01.y);
                *(uint32_t*)&g_Vh[base + (size_t)(s + 8) * 64] = pack_h2(v23.x, v23.y);
            } else {
                int half = mode - 4;
                size_t idx0 = (size_t)row * 1024 + half * 512 + col;
                size_t idx1 = idx0 + 8 * 1024;
                float2 r0 = *(const float2*)&inQ[idx0];
                float2 r1 = *(const float2*)&inQ[idx1];
                *(float2*)&g_tmp[idx0] = make_float2(v01.x + r0.x, v01.y + r0.y);
                *(float2*)&g_tmp[idx1] = make_float2(v23.x + r1.x, v23.y + r1.y);
            }
        }
    }
    #undef GFILL
}

// ===========================================================================
// Flash attention (unchanged R13): 1 slab/CTA, 1024 CTAs, LPT, fp16 1-term,
// ex2 softmax, 5 CTAs/SM.
// ===========================================================================
#define AT_K_H(buf) ((buf) * 5120u)
#define AT_V_H(buf) (10240u + (buf) * 9216u)
#define AT_Q_H 10240u
#define ATTN_SMEM 28672

__global__ void __launch_bounds__(128, 5)
attn_flash(float* __restrict__ Pout)
{
    extern __shared__ unsigned char sm[];
    const uint32_t smb = smem_u32(sm);

    const int bh = blockIdx.x;
    const int qs = 15 - (int)blockIdx.y;
    const int q0 = qs * 64;
    const int nkt = qs + 1;
    const int ncol = nkt * 64;
    const int tid = threadIdx.x, wid = tid >> 5, lane = tid & 31;

    const int frow = tid >> 1;
    const int fs2  = (tid & 1) * 2;
    const int fs4  = (tid & 1) * 4;

#define KFILL(buf, kt)                                                            \
    {                                                                             \
        const __half* sh_ = g_K1h + ((size_t)bh*1024 + (size_t)(kt)*64 + frow)*32 + fs2*8; \
        uint32_t d_ = (uint32_t)(frow * 80 + fs2 * 16);                           \
        cp16(smb + AT_K_H(buf) + d_,      sh_);                                   \
        cp16(smb + AT_K_H(buf) + d_ + 16, sh_ + 8);                               \
    }
#define VFILL(buf, kt)                                                            \
    {                                                                             \
        const __half* sh_ = g_Vh + ((size_t)bh*1024 + (size_t)(kt)*64 + frow)*64 + fs4*8; \
        uint32_t d_ = (uint32_t)(frow * 144 + fs4 * 16);                          \
        _Pragma("unroll")                                                         \
        for (int u_ = 0; u_ < 4; ++u_)                                            \
            cp16(smb + AT_V_H(buf) + d_ + u_*16, sh_ + u_*8);                     \
    }

    KFILL(0, 0); CP_COMMIT();

    {
        const __half* qh = g_Q1h + ((size_t)bh*1024 + q0 + frow)*32 + fs2*8;
        uint32_t d = (uint32_t)(frow * 80 + fs2 * 16);
        *(uint4*)(sm + AT_Q_H + d)      = *(const uint4*)qh;
        *(uint4*)(sm + AT_Q_H + d + 16) = *(const uint4*)(qh + 8);
    }
    __syncthreads();

    uint32_t qfh[2][4];
    #pragma unroll
    for (int ks = 0; ks < 2; ++ks) {
        uint32_t off = (uint32_t)((wid * 16 + (lane & 15)) * 80
                                  + ks * 32 + ((lane >> 4) & 1) * 16);
        ldsm_x4(qfh[ks][0], qfh[ks][1], qfh[ks][2], qfh[ks][3], smb + AT_Q_H + off);
    }

    const int gr0 = q0 + wid * 16 + (lane >> 2);
    const uint32_t kfoff = (uint32_t)(((lane & 7)) * 80 + (lane >> 3) * 16);

    #define SCOMP(buf)                                                            \
    {                                                                             \
        const uint32_t khb = smb + AT_K_H(buf) + kfoff;                           \
        _Pragma("unroll")                                                         \
        for (int nt = 0; nt < 8; ++nt) {                                          \
            uint32_t kb[4];                                                       \
            ldsm_x4(kb[0], kb[1], kb[2], kb[3], khb + (uint32_t)(nt * 8 * 80));   \
            mma_f16(s[nt], qfh[0][0], qfh[0][1], qfh[0][2], qfh[0][3], kb[0], kb[1]); \
            mma_f16(s[nt], qfh[1][0], qfh[1][1], qfh[1][2], qfh[1][3], kb[2], kb[3]); \
        }                                                                         \
    }
    #define SMASK(kt)                                                             \
    if ((kt) == nkt - 1) {                                                        \
        int cb = (kt) * 64 + (lane & 3) * 2;                                      \
        _Pragma("unroll")                                                         \
        for (int nt = 0; nt < 8; ++nt) {                                          \
            int c0 = cb + nt * 8;                                                 \
            if (c0     > gr0)     s[nt][0] = -1e30f;                              \
            if (c0 + 1 > gr0)     s[nt][1] = -1e30f;                              \
            if (c0     > gr0 + 8) s[nt][2] = -1e30f;                              \
            if (c0 + 1 > gr0 + 8) s[nt][3] = -1e30f;                              \
        }                                                                         \
    }

    // ================= Pass 1: l = sum exp2(s) =================
    float l0 = 0.f, l1 = 0.f;

    for (int kt = 0; kt < nkt; ++kt) {
        CP_WAIT(0);
        __syncthreads();
        if (kt + 1 < nkt) { KFILL((kt + 1) & 1, kt + 1); CP_COMMIT(); }

        float s[8][4] = {};
        SCOMP(kt & 1);
        SMASK(kt);

        float a0 = 0.f, a1 = 0.f;
        #pragma unroll
        for (int nt = 0; nt < 8; ++nt) {
            a0 += ex2f(s[nt][0]) + ex2f(s[nt][1]);
            a1 += ex2f(s[nt][2]) + ex2f(s[nt][3]);
        }
        a0 += __shfl_xor_sync(0xffffffffu, a0, 1);
        a0 += __shfl_xor_sync(0xffffffffu, a0, 2);
        a1 += __shfl_xor_sync(0xffffffffu, a1, 1);
        a1 += __shfl_xor_sync(0xffffffffu, a1, 2);
        l0 += a0;
        l1 += a1;
    }
    const float li0 = 1.0f / l0, li1 = 1.0f / l1;

    // ================= Pass 2: P write + O = P @ V =================
    __syncthreads();
    KFILL(0, 0); VFILL(0, 0); CP_COMMIT();

    float o[8][4] = {};

    for (int kt = 0; kt < nkt; ++kt) {
        CP_WAIT(0);
        __syncthreads();
        if (kt + 1 < nkt) {
            KFILL((kt + 1) & 1, kt + 1);
            VFILL((kt + 1) & 1, kt + 1);
            CP_COMMIT();
        }

        float s[8][4] = {};
        SCOMP(kt & 1);
        SMASK(kt);

        #pragma unroll
        for (int nt = 0; nt < 8; ++nt) {
            s[nt][0] = ex2f(s[nt][0]) * li0;
            s[nt][1] = ex2f(s[nt][1]) * li0;
            s[nt][2] = ex2f(s[nt][2]) * li1;
            s[nt][3] = ex2f(s[nt][3]) * li1;
        }

        {
            float* pr0 = Pout + ((size_t)bh * 1024 + gr0) * 1024 + kt * 64 + (lane & 3) * 2;
            float* pr1 = pr0 + 8 * 1024;
            #pragma unroll
            for (int nt = 0; nt < 8; ++nt) {
                *(float2*)&pr0[nt * 8] = make_float2(s[nt][0], s[nt][1]);
                *(float2*)&pr1[nt * 8] = make_float2(s[nt][2], s[nt][3]);
            }
        }

        const uint32_t vhb = smb + AT_V_H(kt & 1);
        #pragma unroll
        for (int ksv = 0; ksv < 4; ++ksv) {
            uint32_t ah[4];
            ah[0] = pack_h2(s[2*ksv][0],   s[2*ksv][1]);
            ah[1] = pack_h2(s[2*ksv][2],   s[2*ksv][3]);
            ah[2] = pack_h2(s[2*ksv+1][0], s[2*ksv+1][1]);
            ah[3] = pack_h2(s[2*ksv+1][2], s[2*ksv+1][3]);
            uint32_t vrow = (uint32_t)((ksv * 16 + (lane & 7) + ((lane >> 3) & 1) * 8) * 144
                                       + (lane >> 4) * 16);
            #pragma unroll
            for (int ntv = 0; ntv < 8; ntv += 2) {
                uint32_t v0, v1, v2, v3;
                ldsm_x4t(v0, v1, v2, v3, vhb + vrow + ntv * 16);
                mma_f16(o[ntv],     ah[0], ah[1], ah[2], ah[3], v0, v1);
                mma_f16(o[ntv + 1], ah[0], ah[1], ah[2], ah[3], v2, v3);
            }
        }
    }

    // zero-fill P tail
    {
        float4 z = make_float4(0.f, 0.f, 0.f, 0.f);
        float* base0 = Pout + ((size_t)bh * 1024 + gr0) * 1024;
        float* base1 = base0 + 8 * 1024;
        for (int col = ncol + (lane & 3) * 4; col < 1024; col += 16) {
            *(float4*)&base0[col] = z;
            *(float4*)&base1[col] = z;
        }
    }

    // O epilogue -> qkvh (fp16)
    {
        const int b = bh >> 4, h = bh & 15;
        size_t i0 = ((size_t)(b * 1024 + gr0)) * 1024 + h * 64 + (lane & 3) * 2;
        size_t i1 = i0 + 8 * 1024;
        #pragma unroll
        for (int ntv = 0; ntv < 8; ++ntv) {
            *(uint32_t*)&qkvh[i0 + ntv * 8] = pack_h2(o[ntv][0], o[ntv][1]);
            *(uint32_t*)&qkvh[i1 + ntv * 8] = pack_h2(o[ntv][2], o[ntv][3]);
        }
    }
    #undef KFILL
    #undef VFILL
    #undef SCOMP
    #undef SMASK
}

// ---------------------------------------------------------------------------
// LayerNorm (unchanged)
// ---------------------------------------------------------------------------
__global__ void __launch_bounds__(256)
ln_kernel(const float* __restrict__ gamma,
          const float* __restrict__ beta,
          float* __restrict__ out)
{
    const int row = blockIdx.x;
    const int tid = threadIdx.x;
    const int c4  = tid * 4;
    const int hf  = tid >> 7;
    const int wrp = tid >> 5;

    float4 v = *(const float4*)&g_tmp[(size_t)row * 1024 + c4];
    float s  = v.x + v.y + v.z + v.w;
    float sq = v.x*v.x + v.y*v.y + v.z*v.z + v.w*v.w;
    #pragma unroll
    for (int off = 16; off > 0; off >>= 1) {
        s  += __shfl_xor_sync(0xffffffffu, s,  off);
        sq += __shfl_xor_sync(0xffffffffu, sq, off);
    }
    __shared__ float ss[8], sqq[8];
    if ((tid & 31) == 0) { ss[wrp] = s; sqq[wrp] = sq; }
    __syncthreads();
    float tot = 0.f, totq = 0.f;
    #pragma unroll
    for (int w = 0; w < 4; ++w) { tot += ss[hf * 4 + w]; totq += sqq[hf * 4 + w]; }

    float mu  = tot * (1.0f / 512.0f);
    float var = totq * (1.0f / 512.0f) - mu * mu;
    float rstd = rsqrtf(var + 1e-5f);

    int gc = c4 & 511;
    float4 g = *(const float4*)&gamma[gc];
    float4 b = *(const float4*)&beta[gc];
    float4 r;
    r.x = (v.x - mu) * rstd * g.x + b.x;
    r.y = (v.y - mu) * rstd * g.y + b.y;
    r.z = (v.z - mu) * rstd * g.z + b.z;
    r.w = (v.w - mu) * rstd * g.w + b.w;
    *(float4*)&out[(size_t)row * 1024 + c4] = r;
}

// ---------------------------------------------------------------------------
extern "C" void kernel_launch(void* const* d_in, const int* in_sizes, int n_in,
                              void* d_out, int out_size)
{
    const float* inQ  = (const float*)d_in[0];
    const float* inK  = (const float*)d_in[1];
    const float* inV  = (const float*)d_in[2];
    const float* WQ1  = (const float*)d_in[4];
    const float* WK1  = (const float*)d_in[5];
    const float* WV1  = (const float*)d_in[6];
    const float* WV2  = (const float*)d_in[9];
    const float* Wfc1 = (const float*)d_in[10];
    const float* Wfc2 = (const float*)d_in[11];
    const float* ln_g = (const float*)d_in[12];
    const float* ln_b = (const float*)d_in[13];

    float* out  = (float*)d_out;
    float* Pout = out + (size_t)B_ * S_ * D_;

    cudaFuncSetAttribute(attn_flash, cudaFuncAttributeMaxDynamicSharedMemorySize,
                         ATTN_SMEM);
    cudaFuncSetAttribute(mma_gemm, cudaFuncAttributeMaxDynamicSharedMemorySize,
                         GEMM_SMEM);

    // 0) convert GEMM operands to fp16
    presplit<<<dim3(256, 9), 256>>>(inQ, inK, inV, WQ1, WK1, WV1, WV2, Wfc1, Wfc2);
    // 1) projections: Q1, K1, V1, V2 (256x128 tiles, 256 CTAs)
    mma_gemm<<<dim3(16, 4, 4), 512, GEMM_SMEM>>>(inQ, 0);
    // 2) flash attention
    attn_flash<<<dim3(64, 16), 128, ATTN_SMEM>>>(Pout);
    // 3) FC + residual (256x128 tiles, 128 CTAs = single wave)
    mma_gemm<<<dim3(16, 4, 2), 512, GEMM_SMEM>>>(inQ, 4);
    // 4) LayerNorm -> final output
    ln_kernel<<<dim3(B_ * S_), 256>>>(ln_g, ln_b, out);
}